// round 13
// baseline (speedup 1.0000x reference)
#include <cuda_runtime.h>
#include <cuda_bf16.h>
#include <cuda_fp16.h>
#include <math.h>
#include <stdint.h>

#define NPIX 16384          // 128*128
#define QPAD 17024          // 16900 padded positions rounded up to 128 multiple

// ---------------- static device scratch (no allocations allowed) ----------------
__device__ __align__(16) float  g_cc  [512 * NPIX];          // [xu(256) ; Cf(256)] chan-major
__device__ __align__(16) float  g_v   [256 * NPIX];          // v; then CfT
__device__ __align__(16) float  g_u   [256 * NPIX];          // u; then Z[9][1024][256]
__device__ __align__(16) float  g_off [ 18 * NPIX];
__device__ __align__(16) int4   g_idx [9 * NPIX];
__device__ __align__(16) float4 g_wt  [9 * NPIX];
__device__ __align__(16) float  g_bnscale[512];
__device__ __align__(16) float  g_bnbias [512];
// fp16 single-plane operands
__device__ __align__(16) __half g_cfh[QPAD * 256];           // padded Cf map [q][256]
__device__ __align__(16) __half g_xh [1024 * 256];           // x32 transposed [s][256]
__device__ __align__(16) __half g_ul [NPIX * 256];           // uT lo plane (exact-B Cf GEMM)
// workspace: Y[9][QPAD][256] fp16, then famT / up1T fp16 planes
// FH region also hosts llfT before step 11; U1H region hosts uT-hi before step 12.
#define Y_BYTES   ((size_t)9 * QPAD * 256 * 2)
#define PLANE_SZ  ((size_t)NPIX * 256 * 2)
#define FH_OFF    (Y_BYTES)
#define U1H_OFF   (Y_BYTES + PLANE_SZ)
__device__ __align__(16) char g_ws[Y_BYTES + 2 * PLANE_SZ];
// fp16 hi/lo weight planes: dc @0, lc1 @1179648, lc2 @1769472, fm @2359296, fs @2424832
__device__ __align__(16) __half g_Ah[2490368];
__device__ __align__(16) __half g_Al[2490368];

// ---------------- PTX helpers (baseline compute_103 ISA only) ----------------
__device__ __forceinline__ uint32_t smem_u32(const void* p) {
    uint32_t a;
    asm("{ .reg .u64 t; cvta.to.shared.u64 t, %1; cvt.u32.u64 %0, t; }" : "=r"(a) : "l"(p));
    return a;
}
#define CP_ASYNC16(dst, src) \
    asm volatile("cp.async.cg.shared.global [%0], [%1], 16;" :: "r"(dst), "l"(src))
#define CP_ASYNC16Z(dst, src, sz) \
    asm volatile("cp.async.cg.shared.global [%0], [%1], 16, %2;" :: "r"(dst), "l"(src), "r"(sz))
#define CP_COMMIT() asm volatile("cp.async.commit_group;")
#define CP_WAIT2()  asm volatile("cp.async.wait_group 2;" ::: "memory")
#define CP_WAIT1()  asm volatile("cp.async.wait_group 1;" ::: "memory")
#define CP_WAIT0()  asm volatile("cp.async.wait_group 0;" ::: "memory")

__device__ __forceinline__ void ldsm4(uint32_t r[4], uint32_t addr) {
    asm volatile("ldmatrix.sync.aligned.m8n8.x4.shared.b16 {%0,%1,%2,%3}, [%4];"
                 : "=r"(r[0]), "=r"(r[1]), "=r"(r[2]), "=r"(r[3]) : "r"(addr));
}
__device__ __forceinline__ void mma_f16(float c[4], const uint32_t a[4],
                                        uint32_t b0, uint32_t b1) {
    asm volatile("mma.sync.aligned.m16n8k16.row.col.f32.f16.f16.f32 "
                 "{%0,%1,%2,%3}, {%4,%5,%6,%7}, {%8,%9}, {%0,%1,%2,%3};"
                 : "+f"(c[0]), "+f"(c[1]), "+f"(c[2]), "+f"(c[3])
                 : "r"(a[0]), "r"(a[1]), "r"(a[2]), "r"(a[3]), "r"(b0), "r"(b1));
}

// ---------------- BN coefficient precompute ----------------
__global__ void bncoef_k(const float* __restrict__ g1, const float* __restrict__ b1,
                         const float* __restrict__ m1, const float* __restrict__ v1,
                         const float* __restrict__ g2, const float* __restrict__ b2,
                         const float* __restrict__ m2, const float* __restrict__ v2)
{
    int i = threadIdx.x;
    if (i < 256) {
        float s = g1[i] / sqrtf(v1[i] + 1e-5f);
        g_bnscale[i] = s;
        g_bnbias[i]  = b1[i] - m1[i] * s;
    } else {
        int j = i - 256;
        float s = g2[j] / sqrtf(v2[j] + 1e-5f);
        g_bnscale[i] = s;
        g_bnbias[i]  = b2[j] - m2[j] * s;
    }
}

// ---------------- weight fp16 hi/lo split with K permutation: k = kp*C + c ----------------
__global__ void split_perm(const float* __restrict__ w, __half* __restrict__ hi,
                           __half* __restrict__ lo, int C, int n)
{
    int t = blockIdx.x * 256 + threadIdx.x;
    if (t >= n) return;
    int K = C * 9;
    int o = t / K, r = t - o * K;
    int c = r / 9, kp = r - c * 9;
    int dst = o * K + kp * C + c;
    float v = w[t];
    __half h = __float2half(v);
    hi[dst] = h;
    lo[dst] = __float2half(v - __half2float(h));
}

// ---------------- plain weight fp16 hi/lo split (1x1 conv weights) ----------------
__global__ void split1(const float* __restrict__ w, __half* __restrict__ hi,
                       __half* __restrict__ lo, int n)
{
    int t = blockIdx.x * 256 + threadIdx.x;
    if (t >= n) return;
    float v = w[t];
    __half h = __float2half(v);
    hi[t] = h;
    lo[t] = __float2half(v - __half2float(h));
}

// ---------------- bilinear upsample 32x32 -> 128x128, align_corners=True ----------------
__global__ void upsample_k(const float* __restrict__ x)
{
    int t = blockIdx.x * 256 + threadIdx.x;
    int pix = t & (NPIX - 1);
    int c   = t >> 14;
    int oy = pix >> 7, ox = pix & 127;
    const float s = 31.0f / 127.0f;
    float fy = oy * s, fx = ox * s;
    int y0 = (int)floorf(fy); int y1 = min(y0 + 1, 31);
    int x0 = (int)floorf(fx); int x1 = min(x0 + 1, 31);
    float wy = fy - (float)y0;
    float wx = fx - (float)x0;
    const float* xc = x + c * 1024;
    float v00 = xc[y0 * 32 + x0], v01 = xc[y0 * 32 + x1];
    float v10 = xc[y1 * 32 + x0], v11 = xc[y1 * 32 + x1];
    float r0 = v00 * (1.0f - wy) + v10 * wy;
    float r1 = v01 * (1.0f - wy) + v11 * wy;
    g_cc[t] = r0 * (1.0f - wx) + r1 * wx;
}

// ---------------- transpose x: x[c][s] -> xh[s][256] fp16 ----------------
__global__ void transpose_x_h(const float* __restrict__ x)
{
    __shared__ float sm[32][33];
    int s0 = blockIdx.x * 32, c0 = blockIdx.y * 32;
    int tx = threadIdx.x, ty = threadIdx.y;     // 32 x 8
#pragma unroll
    for (int i = 0; i < 4; i++)
        sm[ty + 8 * i][tx] = x[(c0 + ty + 8 * i) * 1024 + s0 + tx];
    __syncthreads();
#pragma unroll
    for (int i = 0; i < 4; i++)
        g_xh[(s0 + ty + 8 * i) * 256 + c0 + tx] = __float2half(sm[tx][ty + 8 * i]);
}

// ---------------- transpose activation [c][NPIX] fp32 -> [pix][256] fp16 (single) -------
__global__ void transpose_act_h(const float* __restrict__ src, __half* __restrict__ dst)
{
    __shared__ float sm[32][33];
    int p0 = blockIdx.x * 32, c0 = blockIdx.y * 32;
    int tx = threadIdx.x, ty = threadIdx.y;     // 32 x 8
#pragma unroll
    for (int i = 0; i < 4; i++)
        sm[ty + 8 * i][tx] = src[(size_t)(c0 + ty + 8 * i) * NPIX + p0 + tx];
    __syncthreads();
#pragma unroll
    for (int i = 0; i < 4; i++)
        dst[(size_t)(p0 + ty + 8 * i) * 256 + c0 + tx] = __float2half(sm[tx][ty + 8 * i]);
}

// ---------------- transpose activation -> fp16 hi + lo planes ----------------
__global__ void transpose_act_h2(const float* __restrict__ src,
                                 __half* __restrict__ hi, __half* __restrict__ lo)
{
    __shared__ float sm[32][33];
    int p0 = blockIdx.x * 32, c0 = blockIdx.y * 32;
    int tx = threadIdx.x, ty = threadIdx.y;     // 32 x 8
#pragma unroll
    for (int i = 0; i < 4; i++)
        sm[ty + 8 * i][tx] = src[(size_t)(c0 + ty + 8 * i) * NPIX + p0 + tx];
    __syncthreads();
#pragma unroll
    for (int i = 0; i < 4; i++) {
        float v = sm[tx][ty + 8 * i];
        __half h = __float2half(v);
        size_t o = (size_t)(p0 + ty + 8 * i) * 256 + c0 + tx;
        hi[o] = h;
        lo[o] = __float2half(v - __half2float(h));
    }
}

// ---------------- per-channel 128x128x128 matmul: u[c] = llf[c] @ v[c] + llf[c] ----------------
__global__ void __launch_bounds__(256, 2) chan_matmul(const float* __restrict__ llf)
{
    const int c = blockIdx.x;
    const float* A = llf + (size_t)c * NPIX;
    const float* B = g_v + (size_t)c * NPIX;
    float*       C = g_u + (size_t)c * NPIX;

    __shared__ float As[16][128];
    __shared__ float Bs[16][128];
    const int tid = threadIdx.x;
    const int ty = tid >> 4, tx = tid & 15;

    float acc[8][8];
#pragma unroll
    for (int i = 0; i < 8; i++)
#pragma unroll
        for (int j = 0; j < 8; j++) acc[i][j] = 0.0f;

    for (int k0 = 0; k0 < 128; k0 += 16) {
#pragma unroll
        for (int l = 0; l < 2; l++) {
            int f = tid + l * 256;
            int ar = f >> 2, akq = f & 3;
            float4 av = *(const float4*)(A + ar * 128 + k0 + akq * 4);
            As[akq * 4 + 0][ar] = av.x;
            As[akq * 4 + 1][ar] = av.y;
            As[akq * 4 + 2][ar] = av.z;
            As[akq * 4 + 3][ar] = av.w;
            int bkr = f >> 5, bcq = f & 31;
            *(float4*)(&Bs[bkr][bcq * 4]) = *(const float4*)(B + (k0 + bkr) * 128 + bcq * 4);
        }
        __syncthreads();
#pragma unroll
        for (int kk = 0; kk < 16; kk++) {
            float ra[8], rb[8];
#pragma unroll
            for (int i = 0; i < 8; i++) ra[i] = As[kk][ty * 8 + i];
#pragma unroll
            for (int j = 0; j < 8; j++) rb[j] = Bs[kk][tx * 8 + j];
#pragma unroll
            for (int i = 0; i < 8; i++)
#pragma unroll
                for (int j = 0; j < 8; j++)
                    acc[i][j] = fmaf(ra[i], rb[j], acc[i][j]);
        }
        __syncthreads();
    }
#pragma unroll
    for (int i = 0; i < 8; i++) {
        int row = ty * 8 + i;
#pragma unroll
        for (int j = 0; j < 8; j++) {
            int col = tx * 8 + j;
            C[row * 128 + col] = acc[i][j] + A[row * 128 + col];
        }
    }
}

// ---------------- offsets conv (implicit im2col): off = p_w(18x4608) @ im2col(cc) + p_b ----
// weights staged in padded smem rows (20 floats) and loaded vectorized -> FFMA-bound
__global__ void __launch_bounds__(512) gemm_off(const float* __restrict__ A,
                                                const float* __restrict__ bias)
{
    const int K = 4608, KG = 1152;
    __shared__ float Ash[4][16][20];
    __shared__ float red[4][18][128];
    int tid  = threadIdx.x;
    int g    = tid >> 7;
    int lane = tid & 127;
    int pix  = blockIdx.x * 128 + lane;
    int h = pix >> 7, w = pix & 127;

    float acc[18];
#pragma unroll
    for (int o = 0; o < 18; o++) acc[o] = 0.0f;

    for (int kc = 0; kc < KG; kc += 16) {
        int k0 = g * KG + kc;
        for (int i = lane; i < 288; i += 128) {
            int o = i / 16, kk = i % 16;
            Ash[g][kk][o] = A[o * K + k0 + kk];
        }
        __syncthreads();
#pragma unroll 4
        for (int kk = 0; kk < 16; kk++) {
            int k = k0 + kk;
            int c = k / 9, r = k - c * 9;
            int kh = r / 3, kw = r - kh * 3;
            int ih = h + kh - 1, iw = w + kw - 1;
            float b = 0.0f;
            if ((unsigned)ih < 128u && (unsigned)iw < 128u)
                b = g_cc[((size_t)c << 14) + (ih << 7) + iw];
#pragma unroll
            for (int o4 = 0; o4 < 4; o4++) {
                float4 w4 = *(const float4*)&Ash[g][kk][o4 * 4];
                acc[o4 * 4 + 0] = fmaf(w4.x, b, acc[o4 * 4 + 0]);
                acc[o4 * 4 + 1] = fmaf(w4.y, b, acc[o4 * 4 + 1]);
                acc[o4 * 4 + 2] = fmaf(w4.z, b, acc[o4 * 4 + 2]);
                acc[o4 * 4 + 3] = fmaf(w4.w, b, acc[o4 * 4 + 3]);
            }
            float2 w2 = *(const float2*)&Ash[g][kk][16];
            acc[16] = fmaf(w2.x, b, acc[16]);
            acc[17] = fmaf(w2.y, b, acc[17]);
        }
        __syncthreads();
    }
#pragma unroll
    for (int o = 0; o < 18; o++) red[g][o][lane] = acc[o];
    __syncthreads();
    if (g == 0) {
#pragma unroll
        for (int o = 0; o < 18; o++) {
            float s = red[0][o][lane] + red[1][o][lane] + red[2][o][lane] + red[3][o][lane]
                    + bias[o];
            g_off[o * NPIX + pix] = s;
        }
    }
}

// ---------------- zero border rows of cfh ----------------
__global__ void border_zero_cf()
{
    int t = blockIdx.x * 256 + threadIdx.x;       // 516 * 256
    if (t >= 516 * 256) return;
    int b = t >> 8, c = t & 255;
    int q;
    if (b < 130)       q = b;
    else if (b < 260)  q = 129 * 130 + (b - 130);
    else {
        int r = b - 260;
        int hh = 1 + (r >> 1);
        int ww = (r & 1) ? 129 : 0;
        q = hh * 130 + ww;
    }
    g_cfh[(size_t)q * 256 + c] = __float2half(0.0f);
}

// ---------------- transpose+pad Cf: cc[256+c][pix] -> cfh[(h+1)*130+w+1][c] fp16 --------
__global__ void transpose_pad_cf()
{
    __shared__ float sm[32][33];
    int h  = blockIdx.x;
    int w0 = blockIdx.y * 32;
    int c0 = blockIdx.z * 32;
    int tx = threadIdx.x, ty = threadIdx.y;   // 32 x 8
#pragma unroll
    for (int i = 0; i < 4; i++)
        sm[ty + 8 * i][tx] =
            g_cc[(size_t)(256 + c0 + ty + 8 * i) * NPIX + h * 128 + w0 + tx];
    __syncthreads();
#pragma unroll
    for (int i = 0; i < 4; i++)
        g_cfh[(size_t)((h + 1) * 130 + (w0 + ty + 8 * i + 1)) * 256 + c0 + tx] =
            __float2half(sm[tx][ty + 8 * i]);
}

// ---------------- deform sampling coords + bilinear weights ----------------
__global__ void coords_k()
{
    int t = blockIdx.x * 256 + threadIdx.x;        // 9*NPIX, layout [k][pix]
    int pix = t & (NPIX - 1);
    int k   = t >> 14;
    int h = pix >> 7, w = pix & 127;
    float pnx = (float)(k / 3 - 1);
    float pny = (float)(k % 3 - 1);
    float px = g_off[k * NPIX + pix]       + pnx + (float)(h + 1);
    float py = g_off[(9 + k) * NPIX + pix] + pny + (float)(w + 1);
    float fx = floorf(px), fy = floorf(py);
    float x0 = fminf(fmaxf(fx,        0.0f), 129.0f);
    float x1 = fminf(fmaxf(fx + 1.0f, 0.0f), 129.0f);
    float y0 = fminf(fmaxf(fy,        0.0f), 129.0f);
    float y1 = fminf(fmaxf(fy + 1.0f, 0.0f), 129.0f);
    float pxc = fminf(fmaxf(px, 0.0f), 129.0f);
    float pyc = fminf(fmaxf(py, 0.0f), 129.0f);
    float glt = (1.0f + (x0 - pxc)) * (1.0f + (y0 - pyc));
    float grb = (1.0f - (x1 - pxc)) * (1.0f - (y1 - pyc));
    float glb = (1.0f + (x0 - pxc)) * (1.0f - (y1 - pyc));
    float grt = (1.0f - (x1 - pxc)) * (1.0f + (y0 - pyc));
    int ix0 = (int)x0, ix1 = (int)x1, iy0 = (int)y0, iy1 = (int)y1;
    g_idx[t] = make_int4(ix0 * 130 + iy0, ix1 * 130 + iy1, ix0 * 130 + iy1, ix1 * 130 + iy0);
    g_wt[t]  = make_float4(glt, grb, glb, grt);
}

// ---------------- gather-sum (Y fp16) -> famT fp16 plane ----------------
__global__ void __launch_bounds__(256) gathersum(const __half* __restrict__ Y,
                                                 const float* __restrict__ CfT)
{
    __shared__ int4   sid[9];
    __shared__ float4 swt[9];
    __half* fh = (__half*)(g_ws + FH_OFF);
    int pix = blockIdx.x;
    int t   = threadIdx.x;
    if (t < 9) {
        sid[t] = g_idx[t * NPIX + pix];
        swt[t] = g_wt [t * NPIX + pix];
    }
    __syncthreads();
    float acc = CfT[(size_t)pix * 256 + t];
#pragma unroll
    for (int kp = 0; kp < 9; kp++) {
        const __half* Yk = Y + (size_t)kp * QPAD * 256;
        int4   id = sid[kp];
        float4 w  = swt[kp];
        acc += w.x * __half2float(Yk[(size_t)id.x * 256 + t])
             + w.y * __half2float(Yk[(size_t)id.y * 256 + t])
             + w.z * __half2float(Yk[(size_t)id.z * 256 + t])
             + w.w * __half2float(Yk[(size_t)id.w * 256 + t]);
    }
    fh[(size_t)pix * 256 + t] = __float2half(acc);
}

// ---------------- HMMA fp16 GEMM ----------------
// NT=2: A = Ah + Al (weights exact);  NT=1: A = Ah only
// BT=2: B = Bh + Bl (activation exact; terms Ah*Bh + Al*Bh + Ah*Bl) -> 4-plane, 2-stage
// EPI 3:  relu(x*e1[row]+e2[row]) -> C[m][NPIX]
// EPI 8:  EPI3 + transposed fp16 plane Ct
// EPI 5:  raw -> transposed fp32 Ct (nbase = zz*nq + bcol)
// EPI 7:  raw + bilinear-upsampled Z (e1 = Z base) -> transposed fp16 Ct
// EPI 9:  raw -> normal store C + transposed fp32 Ct
// EPI 10: sigmoid -> normal store C only
// IMC 1:  B operand is implicit 3x3 im2col over plane [pix][256]
#define BK        32
#define ASTRIDE   40
#define PLANE_B   (128 * ASTRIDE * 2)      // 10240 B
#define GEMM_SMEM (9 * PLANE_B)            // 92160 B (3-stage x 3-plane max)

template<int IMC, int NT, int BT>
__device__ __forceinline__ void issue_stage(
    uint32_t sb, int stage, const __half* __restrict__ pA_h,
    const __half* __restrict__ pA_l, const __half* __restrict__ pB,
    const __half* __restrict__ pBl,
    int sA, int sB, int k0, int tid, int bcol)
{
    const int STG = ((BT == 2) ? 4 : 3) * PLANE_B;
    uint32_t stb = sb + stage * STG;
    int kh = 0, kw = 0, cbase = 0;
    if (IMC) {
        int kp = k0 >> 8;
        kh = kp / 3; kw = kp - kh * 3;
        cbase = k0 & 255;
    }
#pragma unroll
    for (int q = 0; q < 2; q++) {
        int id  = tid * 2 + q;
        int row = id >> 2, seg = id & 3;
        uint32_t doff = (row * ASTRIDE + seg * 8) * 2;
        size_t aoff = (size_t)row * sA + k0 + seg * 8;
        CP_ASYNC16(stb + doff, pA_h + aoff);
        if (NT == 2) CP_ASYNC16(stb + PLANE_B + doff, pA_l + aoff);
        if (IMC) {
            int pix = bcol + row;
            int hh = pix >> 7, ww = pix & 127;
            int ih = hh + kh - 1, iw = ww + kw - 1;
            bool ok = ((unsigned)ih < 128u) && ((unsigned)iw < 128u);
            size_t boff = ok ? ((size_t)(ih * 128 + iw) * 256 + cbase + seg * 8) : 0;
            unsigned sz = ok ? 16u : 0u;
            CP_ASYNC16Z(stb + 2 * PLANE_B + doff, pB + boff, sz);
        } else {
            size_t boff = (size_t)row * sB + k0 + seg * 8;
            CP_ASYNC16(stb + 2 * PLANE_B + doff, pB + boff);
            if (BT == 2) CP_ASYNC16(stb + 3 * PLANE_B + doff, pBl + boff);
        }
    }
    CP_COMMIT();
}

template<int EPI, int IMC, int NT, int BT>
__global__ void __launch_bounds__(256, 2) mma_gemm(
    const __half* __restrict__ Ah, const __half* __restrict__ Al,
    const __half* __restrict__ B, const __half* __restrict__ Bl,
    float* __restrict__ C, void* __restrict__ Ct,
    int K, int sA, int sB, int nq, int zoff,
    const float* __restrict__ e1, const float* __restrict__ e2)
{
    extern __shared__ char sm[];
    uint32_t sb = smem_u32(sm);
    const int tid = threadIdx.x;
    const int wid = tid >> 5, lane = tid & 31;
    const int wr = wid >> 2, wc = wid & 3;
    const int brow = blockIdx.y * 128, bcol = blockIdx.x * 128;
    const int zz = blockIdx.z;
    const int STG  = ((BT == 2) ? 4 : 3) * PLANE_B;
    const int NSTG = (BT == 2) ? 2 : 3;

    const __half* pA_h = Ah + (size_t)brow * sA + zz * 512 + zoff;
    const __half* pA_l = Al + (size_t)brow * sA + zz * 512 + zoff;
    const __half* pB   = IMC ? B : B + (size_t)bcol * sB;
    const __half* pBl  = (BT == 2) ? Bl + (size_t)bcol * sB : nullptr;

    float acc[4][4][4];
#pragma unroll
    for (int i = 0; i < 4; i++)
#pragma unroll
        for (int j = 0; j < 4; j++)
#pragma unroll
            for (int q = 0; q < 4; q++) acc[i][j][q] = 0.0f;

    const int sub = lane >> 3, rr = lane & 7;
    const int am = wr * 64 + (sub & 1) * 8 + rr;
    const int ak = (sub >> 1) * 8;
    const int bn = wc * 32 + (sub >> 1) * 8 + rr;
    const int bk = (sub & 1) * 8;

    const int NC = K / BK;
    issue_stage<IMC, NT, BT>(sb, 0, pA_h, pA_l, pB, pBl, sA, sB, 0, tid, bcol);
    issue_stage<IMC, NT, BT>(sb, 1, pA_h, pA_l, pB, pBl, sA, sB, BK, tid, bcol);

    for (int ci = 0; ci < NC; ci++) {
        if (NSTG == 3) {
            if (ci + 2 < NC) {
                issue_stage<IMC, NT, BT>(sb, (ci + 2) % 3, pA_h, pA_l, pB, pBl,
                                         sA, sB, (ci + 2) * BK, tid, bcol);
                CP_WAIT2();
            } else if (ci + 1 < NC) {
                CP_WAIT1();
            } else {
                CP_WAIT0();
            }
        } else {
            if (ci + 1 < NC) CP_WAIT1(); else CP_WAIT0();
        }
        __syncthreads();

        uint32_t stb = sb + (ci % NSTG) * STG;
#pragma unroll
        for (int ks = 0; ks < 2; ks++) {
            uint32_t ah[4][4], al[4][4], bh[4][2], bl[4][2];
#pragma unroll
            for (int mt = 0; mt < 4; mt++) {
                uint32_t aoff = ((am + mt * 16) * ASTRIDE + ks * 16 + ak) * 2;
                ldsm4(ah[mt], stb + aoff);
                if (NT == 2) ldsm4(al[mt], stb + PLANE_B + aoff);
            }
#pragma unroll
            for (int ntp = 0; ntp < 2; ntp++) {
                uint32_t boff = ((bn + ntp * 16) * ASTRIDE + ks * 16 + bk) * 2;
                uint32_t rh[4];
                ldsm4(rh, stb + 2 * PLANE_B + boff);
                bh[ntp * 2 + 0][0] = rh[0]; bh[ntp * 2 + 0][1] = rh[1];
                bh[ntp * 2 + 1][0] = rh[2]; bh[ntp * 2 + 1][1] = rh[3];
                if (BT == 2) {
                    uint32_t rl[4];
                    ldsm4(rl, stb + 3 * PLANE_B + boff);
                    bl[ntp * 2 + 0][0] = rl[0]; bl[ntp * 2 + 0][1] = rl[1];
                    bl[ntp * 2 + 1][0] = rl[2]; bl[ntp * 2 + 1][1] = rl[3];
                }
            }
#pragma unroll
            for (int mt = 0; mt < 4; mt++)
#pragma unroll
                for (int nt = 0; nt < 4; nt++) {
                    mma_f16(acc[mt][nt], ah[mt], bh[nt][0], bh[nt][1]);
                    if (NT == 2) mma_f16(acc[mt][nt], al[mt], bh[nt][0], bh[nt][1]);
                    if (BT == 2) mma_f16(acc[mt][nt], ah[mt], bl[nt][0], bl[nt][1]);
                }
        }
        __syncthreads();
        if (NSTG == 2 && ci + 2 < NC)
            issue_stage<IMC, NT, BT>(sb, ci % 2, pA_h, pA_l, pB, pBl,
                                     sA, sB, (ci + 2) * BK, tid, bcol);
    }

    // ---------------- epilogue ----------------
    const int gid = lane >> 2, t4 = lane & 3;
    float* smf = (float*)sm;                        // stride 132 -> 67584 B
#pragma unroll
    for (int mt = 0; mt < 4; mt++) {
        int ml = wr * 64 + mt * 16 + gid;
        int m0 = brow + ml;
#pragma unroll
        for (int nt = 0; nt < 4; nt++) {
            int nl = wc * 32 + nt * 8 + t4 * 2;
            int n0 = bcol + nl;
            float v0, v1, v2, v3;
            if (EPI == 5 || EPI == 7 || EPI == 9) {
                v0 = acc[mt][nt][0]; v1 = acc[mt][nt][1];
                v2 = acc[mt][nt][2]; v3 = acc[mt][nt][3];
            } else if (EPI == 10) {
                v0 = 1.0f / (1.0f + expf(-acc[mt][nt][0]));
                v1 = 1.0f / (1.0f + expf(-acc[mt][nt][1]));
                v2 = 1.0f / (1.0f + expf(-acc[mt][nt][2]));
                v3 = 1.0f / (1.0f + expf(-acc[mt][nt][3]));
            } else {
                float s0 = e1[m0], b0 = e2[m0];
                float s1 = e1[m0 + 8], b1 = e2[m0 + 8];
                v0 = fmaxf(acc[mt][nt][0] * s0 + b0, 0.0f);
                v1 = fmaxf(acc[mt][nt][1] * s0 + b0, 0.0f);
                v2 = fmaxf(acc[mt][nt][2] * s1 + b1, 0.0f);
                v3 = fmaxf(acc[mt][nt][3] * s1 + b1, 0.0f);
            }
            if (EPI == 3 || EPI == 8 || EPI == 9 || EPI == 10) {
                *(float2*)(C + (size_t)m0 * NPIX + n0)       = make_float2(v0, v1);
                *(float2*)(C + (size_t)(m0 + 8) * NPIX + n0) = make_float2(v2, v3);
            }
            if (EPI != 3 && EPI != 10) {
                smf[(nl)     * 132 + ml]     = v0;
                smf[(nl + 1) * 132 + ml]     = v1;
                smf[(nl)     * 132 + ml + 8] = v2;
                smf[(nl + 1) * 132 + ml + 8] = v3;
            }
        }
    }
    if (EPI == 3 || EPI == 10) return;
    __syncthreads();

    int4*   sQ = (int4*)(sm + 67584);
    float2* sW = (float2*)(sm + 67584 + 2048);
    if (EPI == 7) {
        if (tid < 128) {
            int q = bcol + tid;
            int4 qq = make_int4(-1, 0, 0, 0);
            float2 ww = make_float2(0.0f, 0.0f);
            if (q < 16900) {
                int i = q / 130, j = q - i * 130;
                if (i >= 1 && i <= 128 && j >= 1 && j <= 128) {
                    int h = i - 1, w = j - 1;
                    float fy = h * (31.0f / 127.0f);
                    float fx = w * (31.0f / 127.0f);
                    int y0 = (int)floorf(fy); int y1 = min(y0 + 1, 31);
                    int x0 = (int)floorf(fx); int x1 = min(x0 + 1, 31);
                    ww = make_float2(fy - (float)y0, fx - (float)x0);
                    qq = make_int4(y0 * 32 + x0, y0 * 32 + x1, y1 * 32 + x0, y1 * 32 + x1);
                }
            }
            sQ[tid] = qq; sW[tid] = ww;
        }
        __syncthreads();
    }

    size_t nbase = (size_t)zz * nq + bcol;
#pragma unroll 4
    for (int i = 0; i < 64; i++) {
        int idx = i * 256 + tid;
        int nl = idx >> 7, ml = idx & 127;
        float v = smf[nl * 132 + ml];
        if (EPI == 7) {
            int4 qq = sQ[nl];
            if (qq.x >= 0) {
                float2 ww = sW[nl];
                const float* Zk = e1 + (size_t)zz * 262144;
                int o = brow + ml;
                float r0 = Zk[qq.x * 256 + o] * (1.0f - ww.x) + Zk[qq.z * 256 + o] * ww.x;
                float r1 = Zk[qq.y * 256 + o] * (1.0f - ww.x) + Zk[qq.w * 256 + o] * ww.x;
                v += r0 * (1.0f - ww.y) + r1 * ww.y;
            }
        }
        if (EPI == 5 || EPI == 9) {
            ((float*)Ct)[(nbase + nl) * 256 + brow + ml] = v;
        } else if (EPI == 7 || EPI == 8) {
            ((__half*)Ct)[(nbase + nl) * 256 + brow + ml] = __float2half(v);
        }
    }
}

// ---------------- host launcher ----------------
extern "C" void kernel_launch(void* const* d_in, const int* in_sizes, int n_in,
                              void* d_out, int out_size)
{
    (void)in_sizes; (void)n_in; (void)out_size;
    const float* x    = (const float*)d_in[0];
    const float* llf  = (const float*)d_in[1];
    const float* fm_w = (const float*)d_in[2];
    const float* fs_w = (const float*)d_in[3];
    const float* p_w  = (const float*)d_in[4];
    const float* p_b  = (const float*)d_in[5];
    const float* dc_w = (const float*)d_in[6];
    const float* lc1w = (const float*)d_in[7];
    const float* g1 = (const float*)d_in[8],  *b1 = (const float*)d_in[9];
    const float* m1 = (const float*)d_in[10], *v1 = (const float*)d_in[11];
    const float* lc2w = (const float*)d_in[12];
    const float* g2 = (const float*)d_in[13], *b2 = (const float*)d_in[14];
    const float* m2 = (const float*)d_in[15], *v2 = (const float*)d_in[16];
    float* out = (float*)d_out;

    float *cc, *vv, *uu, *bns, *bnb;
    __half *Ah, *Al, *cfh, *xh, *ul;
    char* ws;
    cudaGetSymbolAddress((void**)&cc,  g_cc);
    cudaGetSymbolAddress((void**)&vv,  g_v);
    cudaGetSymbolAddress((void**)&uu,  g_u);
    cudaGetSymbolAddress((void**)&bns, g_bnscale);
    cudaGetSymbolAddress((void**)&bnb, g_bnbias);
    cudaGetSymbolAddress((void**)&Ah,  g_Ah);
    cudaGetSymbolAddress((void**)&Al,  g_Al);
    cudaGetSymbolAddress((void**)&cfh, g_cfh);
    cudaGetSymbolAddress((void**)&xh,  g_xh);
    cudaGetSymbolAddress((void**)&ul,  g_ul);
    cudaGetSymbolAddress((void**)&ws,  g_ws);
    __half* Y = (__half*)ws;
    float* Z = uu;                                   // reuse g_u after Cf is done
    __half* fh   = (__half*)(ws + FH_OFF);           // llfT, then famT
    __half* u1h  = (__half*)(ws + U1H_OFF);          // uT-hi, then up1T

    cudaFuncSetAttribute(mma_gemm<3,1,1,1>,  cudaFuncAttributeMaxDynamicSharedMemorySize, GEMM_SMEM);
    cudaFuncSetAttribute(mma_gemm<8,1,1,1>,  cudaFuncAttributeMaxDynamicSharedMemorySize, GEMM_SMEM);
    cudaFuncSetAttribute(mma_gemm<5,0,1,1>,  cudaFuncAttributeMaxDynamicSharedMemorySize, GEMM_SMEM);
    cudaFuncSetAttribute(mma_gemm<7,0,1,1>,  cudaFuncAttributeMaxDynamicSharedMemorySize, GEMM_SMEM);
    cudaFuncSetAttribute(mma_gemm<9,0,2,2>,  cudaFuncAttributeMaxDynamicSharedMemorySize, GEMM_SMEM);
    cudaFuncSetAttribute(mma_gemm<10,0,2,1>, cudaFuncAttributeMaxDynamicSharedMemorySize, GEMM_SMEM);

    // 1. BN coefficients + weight splits + x/llf transposes
    bncoef_k<<<1, 512>>>(g1, b1, m1, v1, g2, b2, m2, v2);
    split_perm<<<(1179648 + 255) / 256, 256>>>(dc_w, Ah, Al, 512, 1179648);
    split_perm<<<(589824 + 255) / 256, 256>>>(lc1w, Ah + 1179648, Al + 1179648, 256, 589824);
    split_perm<<<(589824 + 255) / 256, 256>>>(lc2w, Ah + 1769472, Al + 1769472, 256, 589824);
    split1<<<(65536 + 255) / 256, 256>>>(fm_w, Ah + 2359296, Al + 2359296, 65536);
    split1<<<(65536 + 255) / 256, 256>>>(fs_w, Ah + 2424832, Al + 2424832, 65536);
    transpose_x_h<<<dim3(32, 8), dim3(32, 8)>>>(x);
    transpose_act_h<<<dim3(512, 8), dim3(32, 8)>>>(llf, fh);     // llfT fp16
    // 2. xu -> cc[0:256]
    upsample_k<<<NPIX, 256>>>(x);
    // 3. v = sigmoid(fm_w @ llfT) -> g_v [c][pix]   (HMMA, 2-term)
    mma_gemm<10,0,2,1><<<dim3(128, 2), 256, GEMM_SMEM>>>(
        Ah + 2359296, Al + 2359296, fh, nullptr, vv, nullptr, 256, 256, 256, NPIX, 0,
        nullptr, nullptr);
    // 4. u[c] = llf[c] @ v[c] + llf[c]  (fp32)
    chan_matmul<<<256, 256>>>(llf);
    // 4b. uT fp16 hi + lo (exact)
    transpose_act_h2<<<dim3(512, 8), dim3(32, 8)>>>(uu, u1h, ul);
    // 5. Cf = fs_w @ uT -> cc[256:512] + CfT fp32 -> g_v  (HMMA, weights+B exact)
    mma_gemm<9,0,2,2><<<dim3(128, 2), 256, GEMM_SMEM>>>(
        Ah + 2424832, Al + 2424832, u1h, ul, cc + (size_t)256 * NPIX, vv, 256, 256, 256,
        NPIX, 0, nullptr, nullptr);
    // 6. offsets = p_w @ im2col(cc) + p_b
    gemm_off<<<NPIX / 128, 512>>>(p_w, p_b);
    // 7. Cf pad+transpose -> fp16
    border_zero_cf<<<(516 * 256 + 255) / 256, 256>>>();
    transpose_pad_cf<<<dim3(128, 4, 8), dim3(32, 8)>>>();
    // 8. bilinear coords/weights
    coords_k<<<9 * NPIX / 256, 256>>>();
    // 9. Z[kp] = (dc_w_xu_kp @ x32^T)^T  (tiny GEMM, 1024 cols, 1-term)
    mma_gemm<5,0,1,1><<<dim3(8, 2, 9), 256, GEMM_SMEM>>>(
        Ah, Al, xh, nullptr, nullptr, Z, 256, 4608, 256, 1024, 0, nullptr, nullptr);
    // 10. Y[kp] = (dc_w_cf_kp @ Cfp^T)^T + upsample(Z[kp]) -> fp16 (1-term)
    mma_gemm<7,0,1,1><<<dim3(QPAD / 128, 2, 9), 256, GEMM_SMEM>>>(
        Ah, Al, cfh, nullptr, nullptr, Y, 256, 4608, 256, QPAD, 256, Z, nullptr);
    // 11. famT = gathersum(Y) + CfT -> fp16 plane (overwrites llfT region)
    gathersum<<<NPIX, 256>>>(Y, vv);
    // 12. up1 = relu(bn1(lc1 (*) fam)) -> out + up1T fp16 plane (implicit im2col, 1-term)
    mma_gemm<8,1,1,1><<<dim3(128, 2), 256, GEMM_SMEM>>>(
        Ah + 1179648, Al + 1179648, fh, nullptr, out, u1h, 2304, 2304, 0, NPIX, 0,
        bns, bnb);
    // 13. up2 = relu(bn2(lc2 (*) up1)) -> out[256*NPIX:] (implicit im2col, 1-term)
    mma_gemm<3,1,1,1><<<dim3(128, 2), 256, GEMM_SMEM>>>(
        Ah + 1769472, Al + 1769472, u1h, nullptr, out + (size_t)256 * NPIX, nullptr,
        2304, 2304, 0, NPIX, 0, bns + 256, bnb + 256);
}

// round 15
// speedup vs baseline: 1.1086x; 1.1086x over previous
#include <cuda_runtime.h>
#include <cuda_bf16.h>
#include <cuda_fp16.h>
#include <math.h>
#include <stdint.h>

#define NPIX 16384          // 128*128
#define QPAD 17024          // 16900 padded positions rounded up to 128 multiple

// ---------------- static device scratch (no allocations allowed) ----------------
__device__ __align__(16) float  g_cc  [512 * NPIX];          // [xu(256) ; Cf(256)] chan-major
__device__ __align__(16) float  g_v   [256 * NPIX];          // v; then CfT
__device__ __align__(16) float  g_u   [256 * NPIX];          // u; then Z[9][1024][256]
__device__ __align__(16) float  g_off [ 18 * NPIX];
__device__ __align__(16) int4   g_idx [9 * NPIX];
__device__ __align__(16) float4 g_wt  [9 * NPIX];
__device__ __align__(16) float  g_bnscale[512];
__device__ __align__(16) float  g_bnbias [512];
// fp16 single-plane operands
__device__ __align__(16) __half g_cfh[QPAD * 256];           // padded Cf map [q][256]
__device__ __align__(16) __half g_xh [1024 * 256];           // x32 transposed [s][256]
__device__ __align__(16) __half g_ul [NPIX * 256];           // uT lo plane (exact-B Cf GEMM)
// workspace: Y[9][QPAD][256] fp16, then famT / up1T fp16 planes
#define Y_BYTES   ((size_t)9 * QPAD * 256 * 2)
#define PLANE_SZ  ((size_t)NPIX * 256 * 2)
#define FH_OFF    (Y_BYTES)
#define U1H_OFF   (Y_BYTES + PLANE_SZ)
__device__ __align__(16) char g_ws[Y_BYTES + 2 * PLANE_SZ];
// fp16 hi/lo weight planes: dc @0, lc1 @1179648, lc2 @1769472, fm @2359296, fs @2424832
__device__ __align__(16) __half g_Ah[2490368];
__device__ __align__(16) __half g_Al[2490368];

// ---------------- PTX helpers (baseline compute_103 ISA only) ----------------
__device__ __forceinline__ uint32_t smem_u32(const void* p) {
    uint32_t a;
    asm("{ .reg .u64 t; cvta.to.shared.u64 t, %1; cvt.u32.u64 %0, t; }" : "=r"(a) : "l"(p));
    return a;
}
#define CP_ASYNC16(dst, src) \
    asm volatile("cp.async.cg.shared.global [%0], [%1], 16;" :: "r"(dst), "l"(src))
#define CP_ASYNC16Z(dst, src, sz) \
    asm volatile("cp.async.cg.shared.global [%0], [%1], 16, %2;" :: "r"(dst), "l"(src), "r"(sz))
#define CP_COMMIT() asm volatile("cp.async.commit_group;")
#define CP_WAIT2()  asm volatile("cp.async.wait_group 2;" ::: "memory")
#define CP_WAIT1()  asm volatile("cp.async.wait_group 1;" ::: "memory")
#define CP_WAIT0()  asm volatile("cp.async.wait_group 0;" ::: "memory")

__device__ __forceinline__ void ldsm4(uint32_t r[4], uint32_t addr) {
    asm volatile("ldmatrix.sync.aligned.m8n8.x4.shared.b16 {%0,%1,%2,%3}, [%4];"
                 : "=r"(r[0]), "=r"(r[1]), "=r"(r[2]), "=r"(r[3]) : "r"(addr));
}
__device__ __forceinline__ void mma_f16(float c[4], const uint32_t a[4],
                                        uint32_t b0, uint32_t b1) {
    asm volatile("mma.sync.aligned.m16n8k16.row.col.f32.f16.f16.f32 "
                 "{%0,%1,%2,%3}, {%4,%5,%6,%7}, {%8,%9}, {%0,%1,%2,%3};"
                 : "+f"(c[0]), "+f"(c[1]), "+f"(c[2]), "+f"(c[3])
                 : "r"(a[0]), "r"(a[1]), "r"(a[2]), "r"(a[3]), "r"(b0), "r"(b1));
}

// ---------------- BN coefficient precompute ----------------
__global__ void bncoef_k(const float* __restrict__ g1, const float* __restrict__ b1,
                         const float* __restrict__ m1, const float* __restrict__ v1,
                         const float* __restrict__ g2, const float* __restrict__ b2,
                         const float* __restrict__ m2, const float* __restrict__ v2)
{
    int i = threadIdx.x;
    if (i < 256) {
        float s = g1[i] / sqrtf(v1[i] + 1e-5f);
        g_bnscale[i] = s;
        g_bnbias[i]  = b1[i] - m1[i] * s;
    } else {
        int j = i - 256;
        float s = g2[j] / sqrtf(v2[j] + 1e-5f);
        g_bnscale[i] = s;
        g_bnbias[i]  = b2[j] - m2[j] * s;
    }
}

// ---------------- weight fp16 hi/lo split with K permutation: k = kp*C + c ----------------
__global__ void split_perm(const float* __restrict__ w, __half* __restrict__ hi,
                           __half* __restrict__ lo, int C, int n)
{
    int t = blockIdx.x * 256 + threadIdx.x;
    if (t >= n) return;
    int K = C * 9;
    int o = t / K, r = t - o * K;
    int c = r / 9, kp = r - c * 9;
    int dst = o * K + kp * C + c;
    float v = w[t];
    __half h = __float2half(v);
    hi[dst] = h;
    lo[dst] = __float2half(v - __half2float(h));
}

// ---------------- plain weight fp16 hi/lo split (1x1 conv weights) ----------------
__global__ void split1(const float* __restrict__ w, __half* __restrict__ hi,
                       __half* __restrict__ lo, int n)
{
    int t = blockIdx.x * 256 + threadIdx.x;
    if (t >= n) return;
    float v = w[t];
    __half h = __float2half(v);
    hi[t] = h;
    lo[t] = __float2half(v - __half2float(h));
}

// ---------------- bilinear upsample 32x32 -> 128x128, align_corners=True ----------------
__global__ void upsample_k(const float* __restrict__ x)
{
    int t = blockIdx.x * 256 + threadIdx.x;
    int pix = t & (NPIX - 1);
    int c   = t >> 14;
    int oy = pix >> 7, ox = pix & 127;
    const float s = 31.0f / 127.0f;
    float fy = oy * s, fx = ox * s;
    int y0 = (int)floorf(fy); int y1 = min(y0 + 1, 31);
    int x0 = (int)floorf(fx); int x1 = min(x0 + 1, 31);
    float wy = fy - (float)y0;
    float wx = fx - (float)x0;
    const float* xc = x + c * 1024;
    float v00 = xc[y0 * 32 + x0], v01 = xc[y0 * 32 + x1];
    float v10 = xc[y1 * 32 + x0], v11 = xc[y1 * 32 + x1];
    float r0 = v00 * (1.0f - wy) + v10 * wy;
    float r1 = v01 * (1.0f - wy) + v11 * wy;
    g_cc[t] = r0 * (1.0f - wx) + r1 * wx;
}

// ---------------- transpose x: x[c][s] -> xh[s][256] fp16 ----------------
__global__ void transpose_x_h(const float* __restrict__ x)
{
    __shared__ float sm[32][33];
    int s0 = blockIdx.x * 32, c0 = blockIdx.y * 32;
    int tx = threadIdx.x, ty = threadIdx.y;     // 32 x 8
#pragma unroll
    for (int i = 0; i < 4; i++)
        sm[ty + 8 * i][tx] = x[(c0 + ty + 8 * i) * 1024 + s0 + tx];
    __syncthreads();
#pragma unroll
    for (int i = 0; i < 4; i++)
        g_xh[(s0 + ty + 8 * i) * 256 + c0 + tx] = __float2half(sm[tx][ty + 8 * i]);
}

// ---------------- transpose activation [c][NPIX] fp32 -> [pix][256] fp16 (single) -------
__global__ void transpose_act_h(const float* __restrict__ src, __half* __restrict__ dst)
{
    __shared__ float sm[32][33];
    int p0 = blockIdx.x * 32, c0 = blockIdx.y * 32;
    int tx = threadIdx.x, ty = threadIdx.y;     // 32 x 8
#pragma unroll
    for (int i = 0; i < 4; i++)
        sm[ty + 8 * i][tx] = src[(size_t)(c0 + ty + 8 * i) * NPIX + p0 + tx];
    __syncthreads();
#pragma unroll
    for (int i = 0; i < 4; i++)
        dst[(size_t)(p0 + ty + 8 * i) * 256 + c0 + tx] = __float2half(sm[tx][ty + 8 * i]);
}

// ---------------- transpose activation -> fp16 hi + lo planes ----------------
__global__ void transpose_act_h2(const float* __restrict__ src,
                                 __half* __restrict__ hi, __half* __restrict__ lo)
{
    __shared__ float sm[32][33];
    int p0 = blockIdx.x * 32, c0 = blockIdx.y * 32;
    int tx = threadIdx.x, ty = threadIdx.y;     // 32 x 8
#pragma unroll
    for (int i = 0; i < 4; i++)
        sm[ty + 8 * i][tx] = src[(size_t)(c0 + ty + 8 * i) * NPIX + p0 + tx];
    __syncthreads();
#pragma unroll
    for (int i = 0; i < 4; i++) {
        float v = sm[tx][ty + 8 * i];
        __half h = __float2half(v);
        size_t o = (size_t)(p0 + ty + 8 * i) * 256 + c0 + tx;
        hi[o] = h;
        lo[o] = __float2half(v - __half2float(h));
    }
}

// ---------------- per-channel 128x128x128 matmul: u[c] = llf[c] @ v[c] + llf[c] ----------------
__global__ void __launch_bounds__(256, 2) chan_matmul(const float* __restrict__ llf)
{
    const int c = blockIdx.x;
    const float* A = llf + (size_t)c * NPIX;
    const float* B = g_v + (size_t)c * NPIX;
    float*       C = g_u + (size_t)c * NPIX;

    __shared__ float As[16][128];
    __shared__ float Bs[16][128];
    const int tid = threadIdx.x;
    const int ty = tid >> 4, tx = tid & 15;

    float acc[8][8];
#pragma unroll
    for (int i = 0; i < 8; i++)
#pragma unroll
        for (int j = 0; j < 8; j++) acc[i][j] = 0.0f;

    for (int k0 = 0; k0 < 128; k0 += 16) {
#pragma unroll
        for (int l = 0; l < 2; l++) {
            int f = tid + l * 256;
            int ar = f >> 2, akq = f & 3;
            float4 av = *(const float4*)(A + ar * 128 + k0 + akq * 4);
            As[akq * 4 + 0][ar] = av.x;
            As[akq * 4 + 1][ar] = av.y;
            As[akq * 4 + 2][ar] = av.z;
            As[akq * 4 + 3][ar] = av.w;
            int bkr = f >> 5, bcq = f & 31;
            *(float4*)(&Bs[bkr][bcq * 4]) = *(const float4*)(B + (k0 + bkr) * 128 + bcq * 4);
        }
        __syncthreads();
#pragma unroll
        for (int kk = 0; kk < 16; kk++) {
            float ra[8], rb[8];
#pragma unroll
            for (int i = 0; i < 8; i++) ra[i] = As[kk][ty * 8 + i];
#pragma unroll
            for (int j = 0; j < 8; j++) rb[j] = Bs[kk][tx * 8 + j];
#pragma unroll
            for (int i = 0; i < 8; i++)
#pragma unroll
                for (int j = 0; j < 8; j++)
                    acc[i][j] = fmaf(ra[i], rb[j], acc[i][j]);
        }
        __syncthreads();
    }
#pragma unroll
    for (int i = 0; i < 8; i++) {
        int row = ty * 8 + i;
#pragma unroll
        for (int j = 0; j < 8; j++) {
            int col = tx * 8 + j;
            C[row * 128 + col] = acc[i][j] + A[row * 128 + col];
        }
    }
}

// ---------------- offsets conv fp32, kp-outer loop (hoisted bounds, no div-by-9) --------
// off(18xNPIX) = p_w(18x4608) @ im2col(cc) + p_b
__global__ void __launch_bounds__(512) gemm_off(const float* __restrict__ A,
                                                const float* __restrict__ bias)
{
    const int K = 4608;
    __shared__ float Ash[4][16][20];
    __shared__ float red[4][18][128];
    int tid  = threadIdx.x;
    int g    = tid >> 7;            // channel group 0..3 (128 channels each)
    int lane = tid & 127;
    int pix  = blockIdx.x * 128 + lane;
    int h = pix >> 7, w = pix & 127;

    float acc[18];
#pragma unroll
    for (int o = 0; o < 18; o++) acc[o] = 0.0f;

    for (int kp = 0; kp < 9; kp++) {
        int kh = kp / 3, kw = kp - kh * 3;
        int ih = h + kh - 1, iw = w + kw - 1;
        bool ok = ((unsigned)ih < 128u) && ((unsigned)iw < 128u);
        const float* bptr = g_cc + ((size_t)(g * 128) << 14) + (ih << 7) + iw;
        for (int c0 = 0; c0 < 128; c0 += 16) {
            for (int i = lane; i < 288; i += 128) {
                int o = i / 16, cq = i % 16;
                Ash[g][cq][o] = A[o * K + (g * 128 + c0 + cq) * 9 + kp];
            }
            __syncthreads();
            if (ok) {
#pragma unroll 4
                for (int cq = 0; cq < 16; cq++) {
                    float b = bptr[(size_t)(c0 + cq) << 14];
#pragma unroll
                    for (int o4 = 0; o4 < 4; o4++) {
                        float4 w4 = *(const float4*)&Ash[g][cq][o4 * 4];
                        acc[o4 * 4 + 0] = fmaf(w4.x, b, acc[o4 * 4 + 0]);
                        acc[o4 * 4 + 1] = fmaf(w4.y, b, acc[o4 * 4 + 1]);
                        acc[o4 * 4 + 2] = fmaf(w4.z, b, acc[o4 * 4 + 2]);
                        acc[o4 * 4 + 3] = fmaf(w4.w, b, acc[o4 * 4 + 3]);
                    }
                    float2 w2 = *(const float2*)&Ash[g][cq][16];
                    acc[16] = fmaf(w2.x, b, acc[16]);
                    acc[17] = fmaf(w2.y, b, acc[17]);
                }
            }
            __syncthreads();
        }
    }
#pragma unroll
    for (int o = 0; o < 18; o++) red[g][o][lane] = acc[o];
    __syncthreads();
    if (g == 0) {
#pragma unroll
        for (int o = 0; o < 18; o++) {
            float s = red[0][o][lane] + red[1][o][lane] + red[2][o][lane] + red[3][o][lane]
                    + bias[o];
            g_off[o * NPIX + pix] = s;
        }
    }
}

// ---------------- zero border rows of cfh ----------------
__global__ void border_zero_cf()
{
    int t = blockIdx.x * 256 + threadIdx.x;       // 516 * 256
    if (t >= 516 * 256) return;
    int b = t >> 8, c = t & 255;
    int q;
    if (b < 130)       q = b;
    else if (b < 260)  q = 129 * 130 + (b - 130);
    else {
        int r = b - 260;
        int hh = 1 + (r >> 1);
        int ww = (r & 1) ? 129 : 0;
        q = hh * 130 + ww;
    }
    g_cfh[(size_t)q * 256 + c] = __float2half(0.0f);
}

// ---------------- deform sampling coords + bilinear weights ----------------
__global__ void coords_k()
{
    int t = blockIdx.x * 256 + threadIdx.x;        // 9*NPIX, layout [k][pix]
    int pix = t & (NPIX - 1);
    int k   = t >> 14;
    int h = pix >> 7, w = pix & 127;
    float pnx = (float)(k / 3 - 1);
    float pny = (float)(k % 3 - 1);
    float px = g_off[k * NPIX + pix]       + pnx + (float)(h + 1);
    float py = g_off[(9 + k) * NPIX + pix] + pny + (float)(w + 1);
    float fx = floorf(px), fy = floorf(py);
    float x0 = fminf(fmaxf(fx,        0.0f), 129.0f);
    float x1 = fminf(fmaxf(fx + 1.0f, 0.0f), 129.0f);
    float y0 = fminf(fmaxf(fy,        0.0f), 129.0f);
    float y1 = fminf(fmaxf(fy + 1.0f, 0.0f), 129.0f);
    float pxc = fminf(fmaxf(px, 0.0f), 129.0f);
    float pyc = fminf(fmaxf(py, 0.0f), 129.0f);
    float glt = (1.0f + (x0 - pxc)) * (1.0f + (y0 - pyc));
    float grb = (1.0f - (x1 - pxc)) * (1.0f - (y1 - pyc));
    float glb = (1.0f + (x0 - pxc)) * (1.0f - (y1 - pyc));
    float grt = (1.0f - (x1 - pxc)) * (1.0f + (y0 - pyc));
    int ix0 = (int)x0, ix1 = (int)x1, iy0 = (int)y0, iy1 = (int)y1;
    g_idx[t] = make_int4(ix0 * 130 + iy0, ix1 * 130 + iy1, ix0 * 130 + iy1, ix1 * 130 + iy0);
    g_wt[t]  = make_float4(glt, grb, glb, grt);
}

// ---------------- gather-sum (Y fp16) -> famT fp16 plane ----------------
__global__ void __launch_bounds__(256) gathersum(const __half* __restrict__ Y,
                                                 const float* __restrict__ CfT)
{
    __shared__ int4   sid[9];
    __shared__ float4 swt[9];
    __half* fh = (__half*)(g_ws + FH_OFF);
    int pix = blockIdx.x;
    int t   = threadIdx.x;
    if (t < 9) {
        sid[t] = g_idx[t * NPIX + pix];
        swt[t] = g_wt [t * NPIX + pix];
    }
    __syncthreads();
    float acc = CfT[(size_t)pix * 256 + t];
#pragma unroll
    for (int kp = 0; kp < 9; kp++) {
        const __half* Yk = Y + (size_t)kp * QPAD * 256;
        int4   id = sid[kp];
        float4 w  = swt[kp];
        acc += w.x * __half2float(Yk[(size_t)id.x * 256 + t])
             + w.y * __half2float(Yk[(size_t)id.y * 256 + t])
             + w.z * __half2float(Yk[(size_t)id.z * 256 + t])
             + w.w * __half2float(Yk[(size_t)id.w * 256 + t]);
    }
    fh[(size_t)pix * 256 + t] = __float2half(acc);
}

// ---------------- HMMA fp16 GEMM ----------------
// NT=2: A = Ah + Al (weights exact);  NT=1: A = Ah only
// BT=2: B = Bh + Bl (terms Ah*Bh + Al*Bh + Ah*Bl) -> 4-plane, 2-stage
// IMC 1: B operand is implicit 3x3 im2col over plane [pix][256]
// EPI 3:  relu(x*e1[row]+e2[row]) -> C[m][NPIX]
// EPI 8:  EPI3 + transposed fp16 plane Ct
// EPI 5:  raw -> transposed fp32 Ct (nbase = zz*nq + bcol)
// EPI 7:  raw + bilinear-upsampled Z (e1 = Z base) -> transposed fp16 Ct
// EPI 10: sigmoid -> normal store C only
// EPI 12: raw -> normal C + transposed fp32 Ct + padded fp16 g_cfh
#define BK        32
#define ASTRIDE   40
#define PLANE_B   (128 * ASTRIDE * 2)      // 10240 B
#define GEMM_SMEM (9 * PLANE_B)            // 92160 B

template<int IMC, int NT, int BT>
__device__ __forceinline__ void issue_stage(
    uint32_t sb, int stage, const __half* __restrict__ pA_h,
    const __half* __restrict__ pA_l, const __half* __restrict__ pB,
    const __half* __restrict__ pBl,
    int sA, int sB, int k0, int tid, int bcol)
{
    const int STG = ((BT == 2) ? 4 : 3) * PLANE_B;
    uint32_t stb = sb + stage * STG;
    int kh = 0, kw = 0, cbase = 0;
    if (IMC) {
        int kp = k0 >> 8;
        kh = kp / 3; kw = kp - kh * 3;
        cbase = k0 & 255;
    }
#pragma unroll
    for (int q = 0; q < 2; q++) {
        int id  = tid * 2 + q;
        int row = id >> 2, seg = id & 3;
        uint32_t doff = (row * ASTRIDE + seg * 8) * 2;
        size_t aoff = (size_t)row * sA + k0 + seg * 8;
        CP_ASYNC16(stb + doff, pA_h + aoff);
        if (NT == 2) CP_ASYNC16(stb + PLANE_B + doff, pA_l + aoff);
        if (IMC) {
            int pix = bcol + row;
            int hh = pix >> 7, ww = pix & 127;
            int ih = hh + kh - 1, iw = ww + kw - 1;
            bool ok = ((unsigned)ih < 128u) && ((unsigned)iw < 128u);
            size_t boff = ok ? ((size_t)(ih * 128 + iw) * 256 + cbase + seg * 8) : 0;
            unsigned sz = ok ? 16u : 0u;
            CP_ASYNC16Z(stb + 2 * PLANE_B + doff, pB + boff, sz);
        } else {
            size_t boff = (size_t)row * sB + k0 + seg * 8;
            CP_ASYNC16(stb + 2 * PLANE_B + doff, pB + boff);
            if (BT == 2) CP_ASYNC16(stb + 3 * PLANE_B + doff, pBl + boff);
        }
    }
    CP_COMMIT();
}

template<int EPI, int IMC, int NT, int BT>
__global__ void __launch_bounds__(256, 2) mma_gemm(
    const __half* __restrict__ Ah, const __half* __restrict__ Al,
    const __half* __restrict__ B, const __half* __restrict__ Bl,
    float* __restrict__ C, void* __restrict__ Ct,
    int K, int sA, int sB, int nq, int zoff,
    const float* __restrict__ e1, const float* __restrict__ e2)
{
    extern __shared__ char sm[];
    uint32_t sb = smem_u32(sm);
    const int tid = threadIdx.x;
    const int wid = tid >> 5, lane = tid & 31;
    const int wr = wid >> 2, wc = wid & 3;
    const int brow = blockIdx.y * 128, bcol = blockIdx.x * 128;
    const int zz = blockIdx.z;
    const int STG  = ((BT == 2) ? 4 : 3) * PLANE_B;
    const int NSTG = (BT == 2) ? 2 : 3;

    const __half* pA_h = Ah + (size_t)brow * sA + zz * 512 + zoff;
    const __half* pA_l = Al + (size_t)brow * sA + zz * 512 + zoff;
    const __half* pB   = IMC ? B : B + (size_t)bcol * sB;
    const __half* pBl  = (BT == 2) ? Bl + (size_t)bcol * sB : nullptr;

    float acc[4][4][4];
#pragma unroll
    for (int i = 0; i < 4; i++)
#pragma unroll
        for (int j = 0; j < 4; j++)
#pragma unroll
            for (int q = 0; q < 4; q++) acc[i][j][q] = 0.0f;

    const int sub = lane >> 3, rr = lane & 7;
    const int am = wr * 64 + (sub & 1) * 8 + rr;
    const int ak = (sub >> 1) * 8;
    const int bn = wc * 32 + (sub >> 1) * 8 + rr;
    const int bk = (sub & 1) * 8;

    const int NC = K / BK;
    issue_stage<IMC, NT, BT>(sb, 0, pA_h, pA_l, pB, pBl, sA, sB, 0, tid, bcol);
    issue_stage<IMC, NT, BT>(sb, 1, pA_h, pA_l, pB, pBl, sA, sB, BK, tid, bcol);

    for (int ci = 0; ci < NC; ci++) {
        if (NSTG == 3) {
            if (ci + 2 < NC) {
                issue_stage<IMC, NT, BT>(sb, (ci + 2) % 3, pA_h, pA_l, pB, pBl,
                                         sA, sB, (ci + 2) * BK, tid, bcol);
                CP_WAIT2();
            } else if (ci + 1 < NC) {
                CP_WAIT1();
            } else {
                CP_WAIT0();
            }
        } else {
            if (ci + 1 < NC) CP_WAIT1(); else CP_WAIT0();
        }
        __syncthreads();

        uint32_t stb = sb + (ci % NSTG) * STG;
#pragma unroll
        for (int ks = 0; ks < 2; ks++) {
            uint32_t ah[4][4], al[4][4], bh[4][2], bl[4][2];
#pragma unroll
            for (int mt = 0; mt < 4; mt++) {
                uint32_t aoff = ((am + mt * 16) * ASTRIDE + ks * 16 + ak) * 2;
                ldsm4(ah[mt], stb + aoff);
                if (NT == 2) ldsm4(al[mt], stb + PLANE_B + aoff);
            }
#pragma unroll
            for (int ntp = 0; ntp < 2; ntp++) {
                uint32_t boff = ((bn + ntp * 16) * ASTRIDE + ks * 16 + bk) * 2;
                uint32_t rh[4];
                ldsm4(rh, stb + 2 * PLANE_B + boff);
                bh[ntp * 2 + 0][0] = rh[0]; bh[ntp * 2 + 0][1] = rh[1];
                bh[ntp * 2 + 1][0] = rh[2]; bh[ntp * 2 + 1][1] = rh[3];
                if (BT == 2) {
                    uint32_t rl[4];
                    ldsm4(rl, stb + 3 * PLANE_B + boff);
                    bl[ntp * 2 + 0][0] = rl[0]; bl[ntp * 2 + 0][1] = rl[1];
                    bl[ntp * 2 + 1][0] = rl[2]; bl[ntp * 2 + 1][1] = rl[3];
                }
            }
#pragma unroll
            for (int mt = 0; mt < 4; mt++)
#pragma unroll
                for (int nt = 0; nt < 4; nt++) {
                    mma_f16(acc[mt][nt], ah[mt], bh[nt][0], bh[nt][1]);
                    if (NT == 2) mma_f16(acc[mt][nt], al[mt], bh[nt][0], bh[nt][1]);
                    if (BT == 2) mma_f16(acc[mt][nt], ah[mt], bl[nt][0], bl[nt][1]);
                }
        }
        __syncthreads();
        if (NSTG == 2 && ci + 2 < NC)
            issue_stage<IMC, NT, BT>(sb, ci % 2, pA_h, pA_l, pB, pBl,
                                     sA, sB, (ci + 2) * BK, tid, bcol);
    }

    // ---------------- epilogue ----------------
    const int gid = lane >> 2, t4 = lane & 3;
    float* smf = (float*)sm;                        // stride 132 -> 67584 B
#pragma unroll
    for (int mt = 0; mt < 4; mt++) {
        int ml = wr * 64 + mt * 16 + gid;
        int m0 = brow + ml;
#pragma unroll
        for (int nt = 0; nt < 4; nt++) {
            int nl = wc * 32 + nt * 8 + t4 * 2;
            int n0 = bcol + nl;
            float v0, v1, v2, v3;
            if (EPI == 5 || EPI == 7 || EPI == 12) {
                v0 = acc[mt][nt][0]; v1 = acc[mt][nt][1];
                v2 = acc[mt][nt][2]; v3 = acc[mt][nt][3];
            } else if (EPI == 10) {
                v0 = 1.0f / (1.0f + expf(-acc[mt][nt][0]));
                v1 = 1.0f / (1.0f + expf(-acc[mt][nt][1]));
                v2 = 1.0f / (1.0f + expf(-acc[mt][nt][2]));
                v3 = 1.0f / (1.0f + expf(-acc[mt][nt][3]));
            } else {
                float s0 = e1[m0], b0 = e2[m0];
                float s1 = e1[m0 + 8], b1 = e2[m0 + 8];
                v0 = fmaxf(acc[mt][nt][0] * s0 + b0, 0.0f);
                v1 = fmaxf(acc[mt][nt][1] * s0 + b0, 0.0f);
                v2 = fmaxf(acc[mt][nt][2] * s1 + b1, 0.0f);
                v3 = fmaxf(acc[mt][nt][3] * s1 + b1, 0.0f);
            }
            if (EPI == 3 || EPI == 8 || EPI == 10 || EPI == 12) {
                *(float2*)(C + (size_t)m0 * NPIX + n0)       = make_float2(v0, v1);
                *(float2*)(C + (size_t)(m0 + 8) * NPIX + n0) = make_float2(v2, v3);
            }
            if (EPI != 3 && EPI != 10) {
                smf[(nl)     * 132 + ml]     = v0;
                smf[(nl + 1) * 132 + ml]     = v1;
                smf[(nl)     * 132 + ml + 8] = v2;
                smf[(nl + 1) * 132 + ml + 8] = v3;
            }
        }
    }
    if (EPI == 3 || EPI == 10) return;
    __syncthreads();

    int4*   sQ = (int4*)(sm + 67584);
    float2* sW = (float2*)(sm + 67584 + 2048);
    if (EPI == 7) {
        if (tid < 128) {
            int q = bcol + tid;
            int4 qq = make_int4(-1, 0, 0, 0);
            float2 ww = make_float2(0.0f, 0.0f);
            if (q < 16900) {
                int i = q / 130, j = q - i * 130;
                if (i >= 1 && i <= 128 && j >= 1 && j <= 128) {
                    int h = i - 1, w = j - 1;
                    float fy = h * (31.0f / 127.0f);
                    float fx = w * (31.0f / 127.0f);
                    int y0 = (int)floorf(fy); int y1 = min(y0 + 1, 31);
                    int x0 = (int)floorf(fx); int x1 = min(x0 + 1, 31);
                    ww = make_float2(fy - (float)y0, fx - (float)x0);
                    qq = make_int4(y0 * 32 + x0, y0 * 32 + x1, y1 * 32 + x0, y1 * 32 + x1);
                }
            }
            sQ[tid] = qq; sW[tid] = ww;
        }
        __syncthreads();
    }

    size_t nbase = (size_t)zz * nq + bcol;
#pragma unroll 4
    for (int i = 0; i < 64; i++) {
        int idx = i * 256 + tid;
        int nl = idx >> 7, ml = idx & 127;
        float v = smf[nl * 132 + ml];
        if (EPI == 7) {
            int4 qq = sQ[nl];
            if (qq.x >= 0) {
                float2 ww = sW[nl];
                const float* Zk = e1 + (size_t)zz * 262144;
                int o = brow + ml;
                float r0 = Zk[qq.x * 256 + o] * (1.0f - ww.x) + Zk[qq.z * 256 + o] * ww.x;
                float r1 = Zk[qq.y * 256 + o] * (1.0f - ww.x) + Zk[qq.w * 256 + o] * ww.x;
                v += r0 * (1.0f - ww.y) + r1 * ww.y;
            }
        }
        if (EPI == 5) {
            ((float*)Ct)[(nbase + nl) * 256 + brow + ml] = v;
        } else if (EPI == 12) {
            int pix = bcol + nl;
            ((float*)Ct)[(size_t)pix * 256 + brow + ml] = v;
            int hh = pix >> 7, ww = pix & 127;
            g_cfh[(size_t)((hh + 1) * 130 + ww + 1) * 256 + brow + ml] = __float2half(v);
        } else if (EPI == 7 || EPI == 8) {
            ((__half*)Ct)[(nbase + nl) * 256 + brow + ml] = __float2half(v);
        }
    }
}

// ---------------- host launcher ----------------
extern "C" void kernel_launch(void* const* d_in, const int* in_sizes, int n_in,
                              void* d_out, int out_size)
{
    (void)in_sizes; (void)n_in; (void)out_size;
    const float* x    = (const float*)d_in[0];
    const float* llf  = (const float*)d_in[1];
    const float* fm_w = (const float*)d_in[2];
    const float* fs_w = (const float*)d_in[3];
    const float* p_w  = (const float*)d_in[4];
    const float* p_b  = (const float*)d_in[5];
    const float* dc_w = (const float*)d_in[6];
    const float* lc1w = (const float*)d_in[7];
    const float* g1 = (const float*)d_in[8],  *b1 = (const float*)d_in[9];
    const float* m1 = (const float*)d_in[10], *v1 = (const float*)d_in[11];
    const float* lc2w = (const float*)d_in[12];
    const float* g2 = (const float*)d_in[13], *b2 = (const float*)d_in[14];
    const float* m2 = (const float*)d_in[15], *v2 = (const float*)d_in[16];
    float* out = (float*)d_out;

    float *cc, *vv, *uu, *bns, *bnb;
    __half *Ah, *Al, *cfh, *xh, *ul;
    char* ws;
    cudaGetSymbolAddress((void**)&cc,  g_cc);
    cudaGetSymbolAddress((void**)&vv,  g_v);
    cudaGetSymbolAddress((void**)&uu,  g_u);
    cudaGetSymbolAddress((void**)&bns, g_bnscale);
    cudaGetSymbolAddress((void**)&bnb, g_bnbias);
    cudaGetSymbolAddress((void**)&Ah,  g_Ah);
    cudaGetSymbolAddress((void**)&Al,  g_Al);
    cudaGetSymbolAddress((void**)&cfh, g_cfh);
    cudaGetSymbolAddress((void**)&xh,  g_xh);
    cudaGetSymbolAddress((void**)&ul,  g_ul);
    cudaGetSymbolAddress((void**)&ws,  g_ws);
    __half* Y = (__half*)ws;
    float* Z = uu;                                   // reuse g_u after Cf is done
    __half* fh   = (__half*)(ws + FH_OFF);           // llfT, then famT
    __half* u1h  = (__half*)(ws + U1H_OFF);          // uT-hi, then up1T

    cudaFuncSetAttribute(mma_gemm<3,1,1,1>,  cudaFuncAttributeMaxDynamicSharedMemorySize, GEMM_SMEM);
    cudaFuncSetAttribute(mma_gemm<8,1,1,1>,  cudaFuncAttributeMaxDynamicSharedMemorySize, GEMM_SMEM);
    cudaFuncSetAttribute(mma_gemm<5,0,1,1>,  cudaFuncAttributeMaxDynamicSharedMemorySize, GEMM_SMEM);
    cudaFuncSetAttribute(mma_gemm<7,0,1,1>,  cudaFuncAttributeMaxDynamicSharedMemorySize, GEMM_SMEM);
    cudaFuncSetAttribute(mma_gemm<12,0,2,2>, cudaFuncAttributeMaxDynamicSharedMemorySize, GEMM_SMEM);
    cudaFuncSetAttribute(mma_gemm<10,0,2,1>, cudaFuncAttributeMaxDynamicSharedMemorySize, GEMM_SMEM);

    // 1. BN coefficients + weight splits + x/llf transposes
    bncoef_k<<<1, 512>>>(g1, b1, m1, v1, g2, b2, m2, v2);
    split_perm<<<(1179648 + 255) / 256, 256>>>(dc_w, Ah, Al, 512, 1179648);
    split_perm<<<(589824 + 255) / 256, 256>>>(lc1w, Ah + 1179648, Al + 1179648, 256, 589824);
    split_perm<<<(589824 + 255) / 256, 256>>>(lc2w, Ah + 1769472, Al + 1769472, 256, 589824);
    split1<<<(65536 + 255) / 256, 256>>>(fm_w, Ah + 2359296, Al + 2359296, 65536);
    split1<<<(65536 + 255) / 256, 256>>>(fs_w, Ah + 2424832, Al + 2424832, 65536);
    transpose_x_h<<<dim3(32, 8), dim3(32, 8)>>>(x);
    transpose_act_h<<<dim3(512, 8), dim3(32, 8)>>>(llf, fh);     // llfT fp16
    border_zero_cf<<<(516 * 256 + 255) / 256, 256>>>();
    // 2. xu -> cc[0:256]
    upsample_k<<<NPIX, 256>>>(x);
    // 3. v = sigmoid(fm_w @ llfT) -> g_v [c][pix]   (HMMA, 2-term)
    mma_gemm<10,0,2,1><<<dim3(128, 2), 256, GEMM_SMEM>>>(
        Ah + 2359296, Al + 2359296, fh, nullptr, vv, nullptr, 256, 256, 256, NPIX, 0,
        nullptr, nullptr);
    // 4. u[c] = llf[c] @ v[c] + llf[c]  (fp32)
    chan_matmul<<<256, 256>>>(llf);
    // 4b. uT fp16 hi + lo (exact)
    transpose_act_h2<<<dim3(512, 8), dim3(32, 8)>>>(uu, u1h, ul);
    // 5. Cf = fs_w @ uT -> cc[256:512] + CfT fp32 -> g_v + padded fp16 cfh (fused)
    mma_gemm<12,0,2,2><<<dim3(128, 2), 256, GEMM_SMEM>>>(
        Ah + 2424832, Al + 2424832, u1h, ul, cc + (size_t)256 * NPIX, vv, 256, 256, 256,
        NPIX, 0, nullptr, nullptr);
    // 6. offsets = p_w @ im2col(cc) + p_b  (fp32, kp-outer)
    gemm_off<<<NPIX / 128, 512>>>(p_w, p_b);
    // 8. bilinear coords/weights
    coords_k<<<9 * NPIX / 256, 256>>>();
    // 9. Z[kp] = (dc_w_xu_kp @ x32^T)^T  (tiny GEMM, 1024 cols, 1-term)
    mma_gemm<5,0,1,1><<<dim3(8, 2, 9), 256, GEMM_SMEM>>>(
        Ah, Al, xh, nullptr, nullptr, Z, 256, 4608, 256, 1024, 0, nullptr, nullptr);
    // 10. Y[kp] = (dc_w_cf_kp @ Cfp^T)^T + upsample(Z[kp]) -> fp16 (1-term)
    mma_gemm<7,0,1,1><<<dim3(QPAD / 128, 2, 9), 256, GEMM_SMEM>>>(
        Ah, Al, cfh, nullptr, nullptr, Y, 256, 4608, 256, QPAD, 256, Z, nullptr);
    // 11. famT = gathersum(Y) + CfT -> fp16 plane (overwrites llfT region)
    gathersum<<<NPIX, 256>>>(Y, vv);
    // 12. up1 = relu(bn1(lc1 (*) fam)) -> out + up1T fp16 plane (implicit im2col, 1-term)
    mma_gemm<8,1,1,1><<<dim3(128, 2), 256, GEMM_SMEM>>>(
        Ah + 1179648, Al + 1179648, fh, nullptr, out, u1h, 2304, 2304, 0, NPIX, 0,
        bns, bnb);
    // 13. up2 = relu(bn2(lc2 (*) up1)) -> out[256*NPIX:] (implicit im2col, 1-term)
    mma_gemm<3,1,1,1><<<dim3(128, 2), 256, GEMM_SMEM>>>(
        Ah + 1769472, Al + 1769472, u1h, nullptr, out + (size_t)256 * NPIX, nullptr,
        2304, 2304, 0, NPIX, 0, bns + 256, bnb + 256);
}

// round 16
// speedup vs baseline: 1.1869x; 1.0706x over previous
#include <cuda_runtime.h>
#include <cuda_bf16.h>
#include <cuda_fp16.h>
#include <math.h>
#include <stdint.h>

#define NPIX 16384          // 128*128
#define QPAD 17024          // 16900 padded positions rounded up to 128 multiple

// ---------------- static device scratch (no allocations allowed) ----------------
__device__ __align__(16) float  g_cc  [512 * NPIX];          // only [256:512] = Cf used now
__device__ __align__(16) float  g_v   [256 * NPIX];          // v; then CfT
__device__ __align__(16) float  g_u   [256 * NPIX];          // u; then Z[9][1024][256]
__device__ __align__(16) float  g_off [ 18 * NPIX];
__device__ __align__(16) int4   g_idx [9 * NPIX];
__device__ __align__(16) float4 g_wt  [9 * NPIX];
__device__ __align__(16) float  g_bnscale[512];
__device__ __align__(16) float  g_bnbias [512];
__device__ __align__(16) float  g_zoff[9 * 1024 * 32];       // Zoff[kp][s][o<18]
// fp16 single-plane operands
__device__ __align__(16) __half g_cfh[QPAD * 256];           // padded Cf map [q][256]
__device__ __align__(16) __half g_xh [1024 * 256];           // x32 transposed [s][256]
__device__ __align__(16) __half g_ul [NPIX * 256];           // uT lo plane
__device__ __align__(16) __half g_llfh[256 * NPIX];          // llf hi (chan mma A)
__device__ __align__(16) __half g_llfl[256 * NPIX];          // llf lo
__device__ __align__(16) __half g_vth[256 * NPIX];           // v per-channel transposed hi
__device__ __align__(16) __half g_vtl[256 * NPIX];           // v per-channel transposed lo
// workspace: Y[9][QPAD][256] fp16, then famT / up1T fp16 planes
#define Y_BYTES   ((size_t)9 * QPAD * 256 * 2)
#define PLANE_SZ  ((size_t)NPIX * 256 * 2)
#define FH_OFF    (Y_BYTES)
#define U1H_OFF   (Y_BYTES + PLANE_SZ)
__device__ __align__(16) char g_ws[Y_BYTES + 2 * PLANE_SZ];
// fp16 hi/lo weight planes: dc @0, lc1 @1179648, lc2 @1769472, fm @2359296, fs @2424832
__device__ __align__(16) __half g_Ah[2490368];
__device__ __align__(16) __half g_Al[2490368];

// ---------------- PTX helpers (baseline compute_103 ISA only) ----------------
__device__ __forceinline__ uint32_t smem_u32(const void* p) {
    uint32_t a;
    asm("{ .reg .u64 t; cvta.to.shared.u64 t, %1; cvt.u32.u64 %0, t; }" : "=r"(a) : "l"(p));
    return a;
}
#define CP_ASYNC16(dst, src) \
    asm volatile("cp.async.cg.shared.global [%0], [%1], 16;" :: "r"(dst), "l"(src))
#define CP_ASYNC16Z(dst, src, sz) \
    asm volatile("cp.async.cg.shared.global [%0], [%1], 16, %2;" :: "r"(dst), "l"(src), "r"(sz))
#define CP_COMMIT() asm volatile("cp.async.commit_group;")
#define CP_WAIT2()  asm volatile("cp.async.wait_group 2;" ::: "memory")
#define CP_WAIT1()  asm volatile("cp.async.wait_group 1;" ::: "memory")
#define CP_WAIT0()  asm volatile("cp.async.wait_group 0;" ::: "memory")

__device__ __forceinline__ void ldsm4(uint32_t r[4], uint32_t addr) {
    asm volatile("ldmatrix.sync.aligned.m8n8.x4.shared.b16 {%0,%1,%2,%3}, [%4];"
                 : "=r"(r[0]), "=r"(r[1]), "=r"(r[2]), "=r"(r[3]) : "r"(addr));
}
__device__ __forceinline__ void mma_f16(float c[4], const uint32_t a[4],
                                        uint32_t b0, uint32_t b1) {
    asm volatile("mma.sync.aligned.m16n8k16.row.col.f32.f16.f16.f32 "
                 "{%0,%1,%2,%3}, {%4,%5,%6,%7}, {%8,%9}, {%0,%1,%2,%3};"
                 : "+f"(c[0]), "+f"(c[1]), "+f"(c[2]), "+f"(c[3])
                 : "r"(a[0]), "r"(a[1]), "r"(a[2]), "r"(a[3]), "r"(b0), "r"(b1));
}

// ---------------- BN coefficient precompute ----------------
__global__ void bncoef_k(const float* __restrict__ g1, const float* __restrict__ b1,
                         const float* __restrict__ m1, const float* __restrict__ v1,
                         const float* __restrict__ g2, const float* __restrict__ b2,
                         const float* __restrict__ m2, const float* __restrict__ v2)
{
    int i = threadIdx.x;
    if (i < 256) {
        float s = g1[i] / sqrtf(v1[i] + 1e-5f);
        g_bnscale[i] = s;
        g_bnbias[i]  = b1[i] - m1[i] * s;
    } else {
        int j = i - 256;
        float s = g2[j] / sqrtf(v2[j] + 1e-5f);
        g_bnscale[i] = s;
        g_bnbias[i]  = b2[j] - m2[j] * s;
    }
}

// ---------------- weight fp16 hi/lo split with K permutation: k = kp*C + c ----------------
__global__ void split_perm(const float* __restrict__ w, __half* __restrict__ hi,
                           __half* __restrict__ lo, int C, int n)
{
    int t = blockIdx.x * 256 + threadIdx.x;
    if (t >= n) return;
    int K = C * 9;
    int o = t / K, r = t - o * K;
    int c = r / 9, kp = r - c * 9;
    int dst = o * K + kp * C + c;
    float v = w[t];
    __half h = __float2half(v);
    hi[dst] = h;
    lo[dst] = __float2half(v - __half2float(h));
}

// ---------------- plain fp16 hi/lo split ----------------
__global__ void split1(const float* __restrict__ w, __half* __restrict__ hi,
                       __half* __restrict__ lo, int n)
{
    int t = blockIdx.x * 256 + threadIdx.x;
    if (t >= n) return;
    float v = w[t];
    __half h = __float2half(v);
    hi[t] = h;
    lo[t] = __float2half(v - __half2float(h));
}

// ---------------- transpose x: x[c][s] -> xh[s][256] fp16 ----------------
__global__ void transpose_x_h(const float* __restrict__ x)
{
    __shared__ float sm[32][33];
    int s0 = blockIdx.x * 32, c0 = blockIdx.y * 32;
    int tx = threadIdx.x, ty = threadIdx.y;     // 32 x 8
#pragma unroll
    for (int i = 0; i < 4; i++)
        sm[ty + 8 * i][tx] = x[(c0 + ty + 8 * i) * 1024 + s0 + tx];
    __syncthreads();
#pragma unroll
    for (int i = 0; i < 4; i++)
        g_xh[(s0 + ty + 8 * i) * 256 + c0 + tx] = __float2half(sm[tx][ty + 8 * i]);
}

// ---------------- transpose activation [c][NPIX] fp32 -> [pix][256] fp16 (single) -------
__global__ void transpose_act_h(const float* __restrict__ src, __half* __restrict__ dst)
{
    __shared__ float sm[32][33];
    int p0 = blockIdx.x * 32, c0 = blockIdx.y * 32;
    int tx = threadIdx.x, ty = threadIdx.y;     // 32 x 8
#pragma unroll
    for (int i = 0; i < 4; i++)
        sm[ty + 8 * i][tx] = src[(size_t)(c0 + ty + 8 * i) * NPIX + p0 + tx];
    __syncthreads();
#pragma unroll
    for (int i = 0; i < 4; i++)
        dst[(size_t)(p0 + ty + 8 * i) * 256 + c0 + tx] = __float2half(sm[tx][ty + 8 * i]);
}

// ---------------- transpose activation -> fp16 hi + lo planes ----------------
__global__ void transpose_act_h2(const float* __restrict__ src,
                                 __half* __restrict__ hi, __half* __restrict__ lo)
{
    __shared__ float sm[32][33];
    int p0 = blockIdx.x * 32, c0 = blockIdx.y * 32;
    int tx = threadIdx.x, ty = threadIdx.y;     // 32 x 8
#pragma unroll
    for (int i = 0; i < 4; i++)
        sm[ty + 8 * i][tx] = src[(size_t)(c0 + ty + 8 * i) * NPIX + p0 + tx];
    __syncthreads();
#pragma unroll
    for (int i = 0; i < 4; i++) {
        float v = sm[tx][ty + 8 * i];
        __half h = __float2half(v);
        size_t o = (size_t)(p0 + ty + 8 * i) * 256 + c0 + tx;
        hi[o] = h;
        lo[o] = __float2half(v - __half2float(h));
    }
}

// ---------------- per-channel transpose v -> vT fp16 hi/lo: vt[c][a][b] = v[c][b][a] ----
__global__ void transpose_v_h2()
{
    __shared__ float sm[32][33];
    int c  = blockIdx.z;
    int h0 = blockIdx.x * 32, w0 = blockIdx.y * 32;
    int tx = threadIdx.x, ty = threadIdx.y;     // 32 x 8
    const float* src = g_v + (size_t)c * NPIX;
#pragma unroll
    for (int i = 0; i < 4; i++)
        sm[ty + 8 * i][tx] = src[(h0 + ty + 8 * i) * 128 + w0 + tx];
    __syncthreads();
#pragma unroll
    for (int i = 0; i < 4; i++) {
        float v = sm[tx][ty + 8 * i];           // = v[c][h0+tx][w0+ty+8i]
        __half h = __float2half(v);
        size_t o = (size_t)c * NPIX + (w0 + ty + 8 * i) * 128 + h0 + tx;
        g_vth[o] = h;
        g_vtl[o] = __float2half(v - __half2float(h));
    }
}

// ---------------- Zoff[kp][s][o] = sum_c p_w[o][c][kp] * x[c][s]  (fp32, xu half) -------
__global__ void __launch_bounds__(128) zoff_k(const float* __restrict__ pw,
                                              const float* __restrict__ x)
{
    __shared__ float wsm[4608];      // [o][c] 18x256
    int kp = blockIdx.y;
    int s  = blockIdx.x * 128 + threadIdx.x;
    for (int i = threadIdx.x; i < 4608; i += 128) {
        int o = i >> 8, c = i & 255;
        wsm[i] = pw[o * 4608 + c * 9 + kp];
    }
    __syncthreads();
    float acc[18];
#pragma unroll
    for (int o = 0; o < 18; o++) acc[o] = 0.0f;
#pragma unroll 4
    for (int c = 0; c < 256; c++) {
        float xv = x[c * 1024 + s];
#pragma unroll
        for (int o = 0; o < 18; o++) acc[o] = fmaf(wsm[o * 256 + c], xv, acc[o]);
    }
#pragma unroll
    for (int o = 0; o < 18; o++)
        g_zoff[((size_t)kp * 1024 + s) * 32 + o] = acc[o];
}

// ---------------- offsets xu part: static bilinear gather of Zoff -> g_off ----------
__global__ void gather_off()
{
    int o  = threadIdx.x;                       // 0..31, active < 18
    int px = blockIdx.x * 8 + threadIdx.y;
    int h = px >> 7, w = px & 127;
    if (o >= 18) return;
    float acc = 0.0f;
#pragma unroll
    for (int kp = 0; kp < 9; kp++) {
        int kh = kp / 3, kw = kp - kh * 3;
        int ih = h + kh - 1, iw = w + kw - 1;
        if ((unsigned)ih < 128u && (unsigned)iw < 128u) {
            const float sc = 31.0f / 127.0f;
            float fy = ih * sc, fx = iw * sc;
            int y0 = (int)floorf(fy); int y1 = min(y0 + 1, 31);
            int x0 = (int)floorf(fx); int x1 = min(x0 + 1, 31);
            float wy = fy - (float)y0, wx = fx - (float)x0;
            const float* zb = g_zoff + (size_t)kp * 1024 * 32 + o;
            float v00 = zb[(y0 * 32 + x0) * 32], v01 = zb[(y0 * 32 + x1) * 32];
            float v10 = zb[(y1 * 32 + x0) * 32], v11 = zb[(y1 * 32 + x1) * 32];
            float r0 = v00 * (1.0f - wy) + v10 * wy;
            float r1 = v01 * (1.0f - wy) + v11 * wy;
            acc += r0 * (1.0f - wx) + r1 * wx;
        }
    }
    g_off[o * NPIX + px] = acc;
}

// ---------------- offsets Cf part (fp32, kp-outer, K=2304), accumulates onto g_off ------
__global__ void __launch_bounds__(512) gemm_off(const float* __restrict__ A,
                                                const float* __restrict__ bias)
{
    const int K = 4608;
    __shared__ float Ash[4][16][20];
    __shared__ float red[4][18][128];
    int tid  = threadIdx.x;
    int g    = tid >> 7;            // Cf channel group 0..3 (64 channels each)
    int lane = tid & 127;
    int pix  = blockIdx.x * 128 + lane;
    int h = pix >> 7, w = pix & 127;

    float acc[18];
#pragma unroll
    for (int o = 0; o < 18; o++) acc[o] = 0.0f;

    for (int kp = 0; kp < 9; kp++) {
        int kh = kp / 3, kw = kp - kh * 3;
        int ih = h + kh - 1, iw = w + kw - 1;
        bool ok = ((unsigned)ih < 128u) && ((unsigned)iw < 128u);
        const float* bptr = g_cc + ((size_t)(256 + g * 64) << 14) + (ih << 7) + iw;
        for (int c0 = 0; c0 < 64; c0 += 16) {
            for (int i = lane; i < 288; i += 128) {
                int o = i / 16, cq = i % 16;
                Ash[g][cq][o] = A[o * K + (256 + g * 64 + c0 + cq) * 9 + kp];
            }
            __syncthreads();
            if (ok) {
#pragma unroll 4
                for (int cq = 0; cq < 16; cq++) {
                    float b = bptr[(size_t)(c0 + cq) << 14];
#pragma unroll
                    for (int o4 = 0; o4 < 4; o4++) {
                        float4 w4 = *(const float4*)&Ash[g][cq][o4 * 4];
                        acc[o4 * 4 + 0] = fmaf(w4.x, b, acc[o4 * 4 + 0]);
                        acc[o4 * 4 + 1] = fmaf(w4.y, b, acc[o4 * 4 + 1]);
                        acc[o4 * 4 + 2] = fmaf(w4.z, b, acc[o4 * 4 + 2]);
                        acc[o4 * 4 + 3] = fmaf(w4.w, b, acc[o4 * 4 + 3]);
                    }
                    float2 w2 = *(const float2*)&Ash[g][cq][16];
                    acc[16] = fmaf(w2.x, b, acc[16]);
                    acc[17] = fmaf(w2.y, b, acc[17]);
                }
            }
            __syncthreads();
        }
    }
#pragma unroll
    for (int o = 0; o < 18; o++) red[g][o][lane] = acc[o];
    __syncthreads();
    if (g == 0) {
#pragma unroll
        for (int o = 0; o < 18; o++) {
            float s = g_off[o * NPIX + pix]
                    + red[0][o][lane] + red[1][o][lane] + red[2][o][lane] + red[3][o][lane]
                    + bias[o];
            g_off[o * NPIX + pix] = s;
        }
    }
}

// ---------------- zero border rows of cfh ----------------
__global__ void border_zero_cf()
{
    int t = blockIdx.x * 256 + threadIdx.x;       // 516 * 256
    if (t >= 516 * 256) return;
    int b = t >> 8, c = t & 255;
    int q;
    if (b < 130)       q = b;
    else if (b < 260)  q = 129 * 130 + (b - 130);
    else {
        int r = b - 260;
        int hh = 1 + (r >> 1);
        int ww = (r & 1) ? 129 : 0;
        q = hh * 130 + ww;
    }
    g_cfh[(size_t)q * 256 + c] = __float2half(0.0f);
}

// ---------------- deform sampling coords + bilinear weights ----------------
__global__ void coords_k()
{
    int t = blockIdx.x * 256 + threadIdx.x;        // 9*NPIX, layout [k][pix]
    int pix = t & (NPIX - 1);
    int k   = t >> 14;
    int h = pix >> 7, w = pix & 127;
    float pnx = (float)(k / 3 - 1);
    float pny = (float)(k % 3 - 1);
    float px = g_off[k * NPIX + pix]       + pnx + (float)(h + 1);
    float py = g_off[(9 + k) * NPIX + pix] + pny + (float)(w + 1);
    float fx = floorf(px), fy = floorf(py);
    float x0 = fminf(fmaxf(fx,        0.0f), 129.0f);
    float x1 = fminf(fmaxf(fx + 1.0f, 0.0f), 129.0f);
    float y0 = fminf(fmaxf(fy,        0.0f), 129.0f);
    float y1 = fminf(fmaxf(fy + 1.0f, 0.0f), 129.0f);
    float pxc = fminf(fmaxf(px, 0.0f), 129.0f);
    float pyc = fminf(fmaxf(py, 0.0f), 129.0f);
    float glt = (1.0f + (x0 - pxc)) * (1.0f + (y0 - pyc));
    float grb = (1.0f - (x1 - pxc)) * (1.0f - (y1 - pyc));
    float glb = (1.0f + (x0 - pxc)) * (1.0f - (y1 - pyc));
    float grt = (1.0f - (x1 - pxc)) * (1.0f + (y0 - pyc));
    int ix0 = (int)x0, ix1 = (int)x1, iy0 = (int)y0, iy1 = (int)y1;
    g_idx[t] = make_int4(ix0 * 130 + iy0, ix1 * 130 + iy1, ix0 * 130 + iy1, ix1 * 130 + iy0);
    g_wt[t]  = make_float4(glt, grb, glb, grt);
}

// ---------------- gather-sum (Y fp16) -> famT fp16 plane ----------------
__global__ void __launch_bounds__(256) gathersum(const __half* __restrict__ Y,
                                                 const float* __restrict__ CfT)
{
    __shared__ int4   sid[9];
    __shared__ float4 swt[9];
    __half* fh = (__half*)(g_ws + FH_OFF);
    int pix = blockIdx.x;
    int t   = threadIdx.x;
    if (t < 9) {
        sid[t] = g_idx[t * NPIX + pix];
        swt[t] = g_wt [t * NPIX + pix];
    }
    __syncthreads();
    float acc = CfT[(size_t)pix * 256 + t];
#pragma unroll
    for (int kp = 0; kp < 9; kp++) {
        const __half* Yk = Y + (size_t)kp * QPAD * 256;
        int4   id = sid[kp];
        float4 w  = swt[kp];
        acc += w.x * __half2float(Yk[(size_t)id.x * 256 + t])
             + w.y * __half2float(Yk[(size_t)id.y * 256 + t])
             + w.z * __half2float(Yk[(size_t)id.z * 256 + t])
             + w.w * __half2float(Yk[(size_t)id.w * 256 + t]);
    }
    fh[(size_t)pix * 256 + t] = __float2half(acc);
}

// ---------------- HMMA fp16 GEMM ----------------
// NT=2: A = Ah + Al (weights exact);  NT=1: A = Ah only
// BT=2: B = Bh + Bl (terms Ah*Bh + Al*Bh + Ah*Bl) -> 4-plane, 2-stage
// IMC 1: B operand is implicit 3x3 im2col over plane [pix][256]
// EPI 3:  relu(x*e1[row]+e2[row]) -> C[m][NPIX]
// EPI 8:  EPI3 + transposed fp16 plane Ct
// EPI 5:  raw -> transposed fp32 Ct (nbase = zz*nq + bcol)
// EPI 7:  raw + bilinear-upsampled Z (e1 = Z base) -> transposed fp16 Ct
// EPI 10: sigmoid -> normal store C only
// EPI 12: raw -> normal C + transposed fp32 Ct + padded fp16 g_cfh
// EPI 13: per-channel (zz=c): u = acc + e1[zz*NPIX + m*128 + n] -> C[zz*NPIX + m*128+n]
#define BK        32
#define ASTRIDE   40
#define PLANE_B   (128 * ASTRIDE * 2)      // 10240 B
#define GEMM_SMEM (9 * PLANE_B)            // 92160 B

template<int IMC, int NT, int BT>
__device__ __forceinline__ void issue_stage(
    uint32_t sb, int stage, const __half* __restrict__ pA_h,
    const __half* __restrict__ pA_l, const __half* __restrict__ pB,
    const __half* __restrict__ pBl,
    int sA, int sB, int k0, int tid, int bcol)
{
    const int STG = ((BT == 2) ? 4 : 3) * PLANE_B;
    uint32_t stb = sb + stage * STG;
    int kh = 0, kw = 0, cbase = 0;
    if (IMC) {
        int kp = k0 >> 8;
        kh = kp / 3; kw = kp - kh * 3;
        cbase = k0 & 255;
    }
#pragma unroll
    for (int q = 0; q < 2; q++) {
        int id  = tid * 2 + q;
        int row = id >> 2, seg = id & 3;
        uint32_t doff = (row * ASTRIDE + seg * 8) * 2;
        size_t aoff = (size_t)row * sA + k0 + seg * 8;
        CP_ASYNC16(stb + doff, pA_h + aoff);
        if (NT == 2) CP_ASYNC16(stb + PLANE_B + doff, pA_l + aoff);
        if (IMC) {
            int pix = bcol + row;
            int hh = pix >> 7, ww = pix & 127;
            int ih = hh + kh - 1, iw = ww + kw - 1;
            bool ok = ((unsigned)ih < 128u) && ((unsigned)iw < 128u);
            size_t boff = ok ? ((size_t)(ih * 128 + iw) * 256 + cbase + seg * 8) : 0;
            unsigned sz = ok ? 16u : 0u;
            CP_ASYNC16Z(stb + 2 * PLANE_B + doff, pB + boff, sz);
        } else {
            size_t boff = (size_t)row * sB + k0 + seg * 8;
            CP_ASYNC16(stb + 2 * PLANE_B + doff, pB + boff);
            if (BT == 2) CP_ASYNC16(stb + 3 * PLANE_B + doff, pBl + boff);
        }
    }
    CP_COMMIT();
}

template<int EPI, int IMC, int NT, int BT>
__global__ void __launch_bounds__(256, 2) mma_gemm(
    const __half* __restrict__ Ah, const __half* __restrict__ Al,
    const __half* __restrict__ B, const __half* __restrict__ Bl,
    float* __restrict__ C, void* __restrict__ Ct,
    int K, int sA, int sB, int nq, int zstrA, int zstrB,
    const float* __restrict__ e1, const float* __restrict__ e2)
{
    extern __shared__ char sm[];
    uint32_t sb = smem_u32(sm);
    const int tid = threadIdx.x;
    const int wid = tid >> 5, lane = tid & 31;
    const int wr = wid >> 2, wc = wid & 3;
    const int brow = blockIdx.y * 128, bcol = blockIdx.x * 128;
    const int zz = blockIdx.z;
    const int STG  = ((BT == 2) ? 4 : 3) * PLANE_B;
    const int NSTG = (BT == 2) ? 2 : 3;

    const __half* pA_h = Ah + (size_t)brow * sA + (size_t)zz * zstrA;
    const __half* pA_l = Al + (size_t)brow * sA + (size_t)zz * zstrA;
    const __half* pB   = IMC ? B : B + (size_t)bcol * sB + (size_t)zz * zstrB;
    const __half* pBl  = (BT == 2) ? Bl + (size_t)bcol * sB + (size_t)zz * zstrB : nullptr;

    float acc[4][4][4];
#pragma unroll
    for (int i = 0; i < 4; i++)
#pragma unroll
        for (int j = 0; j < 4; j++)
#pragma unroll
            for (int q = 0; q < 4; q++) acc[i][j][q] = 0.0f;

    const int sub = lane >> 3, rr = lane & 7;
    const int am = wr * 64 + (sub & 1) * 8 + rr;
    const int ak = (sub >> 1) * 8;
    const int bn = wc * 32 + (sub >> 1) * 8 + rr;
    const int bk = (sub & 1) * 8;

    const int NC = K / BK;
    issue_stage<IMC, NT, BT>(sb, 0, pA_h, pA_l, pB, pBl, sA, sB, 0, tid, bcol);
    issue_stage<IMC, NT, BT>(sb, 1, pA_h, pA_l, pB, pBl, sA, sB, BK, tid, bcol);

    for (int ci = 0; ci < NC; ci++) {
        if (NSTG == 3) {
            if (ci + 2 < NC) {
                issue_stage<IMC, NT, BT>(sb, (ci + 2) % 3, pA_h, pA_l, pB, pBl,
                                         sA, sB, (ci + 2) * BK, tid, bcol);
                CP_WAIT2();
            } else if (ci + 1 < NC) {
                CP_WAIT1();
            } else {
                CP_WAIT0();
            }
        } else {
            if (ci + 1 < NC) CP_WAIT1(); else CP_WAIT0();
        }
        __syncthreads();

        uint32_t stb = sb + (ci % NSTG) * STG;
#pragma unroll
        for (int ks = 0; ks < 2; ks++) {
            uint32_t ah[4][4], al[4][4], bh[4][2], bl[4][2];
#pragma unroll
            for (int mt = 0; mt < 4; mt++) {
                uint32_t aoff = ((am + mt * 16) * ASTRIDE + ks * 16 + ak) * 2;
                ldsm4(ah[mt], stb + aoff);
                if (NT == 2) ldsm4(al[mt], stb + PLANE_B + aoff);
            }
#pragma unroll
            for (int ntp = 0; ntp < 2; ntp++) {
                uint32_t boff = ((bn + ntp * 16) * ASTRIDE + ks * 16 + bk) * 2;
                uint32_t rh[4];
                ldsm4(rh, stb + 2 * PLANE_B + boff);
                bh[ntp * 2 + 0][0] = rh[0]; bh[ntp * 2 + 0][1] = rh[1];
                bh[ntp * 2 + 1][0] = rh[2]; bh[ntp * 2 + 1][1] = rh[3];
                if (BT == 2) {
                    uint32_t rl[4];
                    ldsm4(rl, stb + 3 * PLANE_B + boff);
                    bl[ntp * 2 + 0][0] = rl[0]; bl[ntp * 2 + 0][1] = rl[1];
                    bl[ntp * 2 + 1][0] = rl[2]; bl[ntp * 2 + 1][1] = rl[3];
                }
            }
#pragma unroll
            for (int mt = 0; mt < 4; mt++)
#pragma unroll
                for (int nt = 0; nt < 4; nt++) {
                    mma_f16(acc[mt][nt], ah[mt], bh[nt][0], bh[nt][1]);
                    if (NT == 2) mma_f16(acc[mt][nt], al[mt], bh[nt][0], bh[nt][1]);
                    if (BT == 2) mma_f16(acc[mt][nt], ah[mt], bl[nt][0], bl[nt][1]);
                }
        }
        __syncthreads();
        if (NSTG == 2 && ci + 2 < NC)
            issue_stage<IMC, NT, BT>(sb, ci % 2, pA_h, pA_l, pB, pBl,
                                     sA, sB, (ci + 2) * BK, tid, bcol);
    }

    // ---------------- epilogue ----------------
    const int gid = lane >> 2, t4 = lane & 3;
    float* smf = (float*)sm;                        // stride 132 -> 67584 B
#pragma unroll
    for (int mt = 0; mt < 4; mt++) {
        int ml = wr * 64 + mt * 16 + gid;
        int m0 = brow + ml;
#pragma unroll
        for (int nt = 0; nt < 4; nt++) {
            int nl = wc * 32 + nt * 8 + t4 * 2;
            int n0 = bcol + nl;
            float v0, v1, v2, v3;
            if (EPI == 5 || EPI == 7 || EPI == 12) {
                v0 = acc[mt][nt][0]; v1 = acc[mt][nt][1];
                v2 = acc[mt][nt][2]; v3 = acc[mt][nt][3];
            } else if (EPI == 10) {
                v0 = 1.0f / (1.0f + expf(-acc[mt][nt][0]));
                v1 = 1.0f / (1.0f + expf(-acc[mt][nt][1]));
                v2 = 1.0f / (1.0f + expf(-acc[mt][nt][2]));
                v3 = 1.0f / (1.0f + expf(-acc[mt][nt][3]));
            } else if (EPI == 13) {
                size_t cb = (size_t)zz * NPIX;
                v0 = acc[mt][nt][0] + e1[cb + (size_t)m0 * 128 + n0];
                v1 = acc[mt][nt][1] + e1[cb + (size_t)m0 * 128 + n0 + 1];
                v2 = acc[mt][nt][2] + e1[cb + (size_t)(m0 + 8) * 128 + n0];
                v3 = acc[mt][nt][3] + e1[cb + (size_t)(m0 + 8) * 128 + n0 + 1];
            } else {
                float s0 = e1[m0], b0 = e2[m0];
                float s1 = e1[m0 + 8], b1 = e2[m0 + 8];
                v0 = fmaxf(acc[mt][nt][0] * s0 + b0, 0.0f);
                v1 = fmaxf(acc[mt][nt][1] * s0 + b0, 0.0f);
                v2 = fmaxf(acc[mt][nt][2] * s1 + b1, 0.0f);
                v3 = fmaxf(acc[mt][nt][3] * s1 + b1, 0.0f);
            }
            if (EPI == 13) {
                size_t cb = (size_t)zz * NPIX;
                *(float2*)(C + cb + (size_t)m0 * 128 + n0)       = make_float2(v0, v1);
                *(float2*)(C + cb + (size_t)(m0 + 8) * 128 + n0) = make_float2(v2, v3);
            } else if (EPI == 3 || EPI == 8 || EPI == 10 || EPI == 12) {
                *(float2*)(C + (size_t)m0 * NPIX + n0)       = make_float2(v0, v1);
                *(float2*)(C + (size_t)(m0 + 8) * NPIX + n0) = make_float2(v2, v3);
            }
            if (EPI != 3 && EPI != 10 && EPI != 13) {
                smf[(nl)     * 132 + ml]     = v0;
                smf[(nl + 1) * 132 + ml]     = v1;
                smf[(nl)     * 132 + ml + 8] = v2;
                smf[(nl + 1) * 132 + ml + 8] = v3;
            }
        }
    }
    if (EPI == 3 || EPI == 10 || EPI == 13) return;
    __syncthreads();

    int4*   sQ = (int4*)(sm + 67584);
    float2* sW = (float2*)(sm + 67584 + 2048);
    if (EPI == 7) {
        if (tid < 128) {
            int q = bcol + tid;
            int4 qq = make_int4(-1, 0, 0, 0);
            float2 ww = make_float2(0.0f, 0.0f);
            if (q < 16900) {
                int i = q / 130, j = q - i * 130;
                if (i >= 1 && i <= 128 && j >= 1 && j <= 128) {
                    int h = i - 1, w = j - 1;
                    float fy = h * (31.0f / 127.0f);
                    float fx = w * (31.0f / 127.0f);
                    int y0 = (int)floorf(fy); int y1 = min(y0 + 1, 31);
                    int x0 = (int)floorf(fx); int x1 = min(x0 + 1, 31);
                    ww = make_float2(fy - (float)y0, fx - (float)x0);
                    qq = make_int4(y0 * 32 + x0, y0 * 32 + x1, y1 * 32 + x0, y1 * 32 + x1);
                }
            }
            sQ[tid] = qq; sW[tid] = ww;
        }
        __syncthreads();
    }

    size_t nbase = (size_t)zz * nq + bcol;
#pragma unroll 4
    for (int i = 0; i < 64; i++) {
        int idx = i * 256 + tid;
        int nl = idx >> 7, ml = idx & 127;
        float v = smf[nl * 132 + ml];
        if (EPI == 7) {
            int4 qq = sQ[nl];
            if (qq.x >= 0) {
                float2 ww = sW[nl];
                const float* Zk = e1 + (size_t)zz * 262144;
                int o = brow + ml;
                float r0 = Zk[qq.x * 256 + o] * (1.0f - ww.x) + Zk[qq.z * 256 + o] * ww.x;
                float r1 = Zk[qq.y * 256 + o] * (1.0f - ww.x) + Zk[qq.w * 256 + o] * ww.x;
                v += r0 * (1.0f - ww.y) + r1 * ww.y;
            }
        }
        if (EPI == 5) {
            ((float*)Ct)[(nbase + nl) * 256 + brow + ml] = v;
        } else if (EPI == 12) {
            int pix = bcol + nl;
            ((float*)Ct)[(size_t)pix * 256 + brow + ml] = v;
            int hh = pix >> 7, ww = pix & 127;
            g_cfh[(size_t)((hh + 1) * 130 + ww + 1) * 256 + brow + ml] = __float2half(v);
        } else if (EPI == 7 || EPI == 8) {
            ((__half*)Ct)[(nbase + nl) * 256 + brow + ml] = __float2half(v);
        }
    }
}

// ---------------- host launcher ----------------
extern "C" void kernel_launch(void* const* d_in, const int* in_sizes, int n_in,
                              void* d_out, int out_size)
{
    (void)in_sizes; (void)n_in; (void)out_size;
    const float* x    = (const float*)d_in[0];
    const float* llf  = (const float*)d_in[1];
    const float* fm_w = (const float*)d_in[2];
    const float* fs_w = (const float*)d_in[3];
    const float* p_w  = (const float*)d_in[4];
    const float* p_b  = (const float*)d_in[5];
    const float* dc_w = (const float*)d_in[6];
    const float* lc1w = (const float*)d_in[7];
    const float* g1 = (const float*)d_in[8],  *b1 = (const float*)d_in[9];
    const float* m1 = (const float*)d_in[10], *v1 = (const float*)d_in[11];
    const float* lc2w = (const float*)d_in[12];
    const float* g2 = (const float*)d_in[13], *b2 = (const float*)d_in[14];
    const float* m2 = (const float*)d_in[15], *v2 = (const float*)d_in[16];
    float* out = (float*)d_out;

    float *cc, *vv, *uu, *bns, *bnb;
    __half *Ah, *Al, *cfh, *xh, *ul, *llfh, *llfl, *vth, *vtl;
    char* ws;
    cudaGetSymbolAddress((void**)&cc,  g_cc);
    cudaGetSymbolAddress((void**)&vv,  g_v);
    cudaGetSymbolAddress((void**)&uu,  g_u);
    cudaGetSymbolAddress((void**)&bns, g_bnscale);
    cudaGetSymbolAddress((void**)&bnb, g_bnbias);
    cudaGetSymbolAddress((void**)&Ah,  g_Ah);
    cudaGetSymbolAddress((void**)&Al,  g_Al);
    cudaGetSymbolAddress((void**)&cfh, g_cfh);
    cudaGetSymbolAddress((void**)&xh,  g_xh);
    cudaGetSymbolAddress((void**)&ul,  g_ul);
    cudaGetSymbolAddress((void**)&llfh, g_llfh);
    cudaGetSymbolAddress((void**)&llfl, g_llfl);
    cudaGetSymbolAddress((void**)&vth, g_vth);
    cudaGetSymbolAddress((void**)&vtl, g_vtl);
    cudaGetSymbolAddress((void**)&ws,  g_ws);
    __half* Y = (__half*)ws;
    float* Z = uu;                                   // reuse g_u after uT extracted
    __half* fh   = (__half*)(ws + FH_OFF);           // llfT, then famT
    __half* u1h  = (__half*)(ws + U1H_OFF);          // uT-hi, then up1T

    cudaFuncSetAttribute(mma_gemm<3,1,1,1>,  cudaFuncAttributeMaxDynamicSharedMemorySize, GEMM_SMEM);
    cudaFuncSetAttribute(mma_gemm<8,1,1,1>,  cudaFuncAttributeMaxDynamicSharedMemorySize, GEMM_SMEM);
    cudaFuncSetAttribute(mma_gemm<5,0,1,1>,  cudaFuncAttributeMaxDynamicSharedMemorySize, GEMM_SMEM);
    cudaFuncSetAttribute(mma_gemm<7,0,1,1>,  cudaFuncAttributeMaxDynamicSharedMemorySize, GEMM_SMEM);
    cudaFuncSetAttribute(mma_gemm<12,0,2,2>, cudaFuncAttributeMaxDynamicSharedMemorySize, GEMM_SMEM);
    cudaFuncSetAttribute(mma_gemm<10,0,2,1>, cudaFuncAttributeMaxDynamicSharedMemorySize, GEMM_SMEM);
    cudaFuncSetAttribute(mma_gemm<13,0,2,2>, cudaFuncAttributeMaxDynamicSharedMemorySize, GEMM_SMEM);

    // 1. prep: BN coeffs, weight splits, transposes, Zoff
    bncoef_k<<<1, 512>>>(g1, b1, m1, v1, g2, b2, m2, v2);
    split_perm<<<(1179648 + 255) / 256, 256>>>(dc_w, Ah, Al, 512, 1179648);
    split_perm<<<(589824 + 255) / 256, 256>>>(lc1w, Ah + 1179648, Al + 1179648, 256, 589824);
    split_perm<<<(589824 + 255) / 256, 256>>>(lc2w, Ah + 1769472, Al + 1769472, 256, 589824);
    split1<<<(65536 + 255) / 256, 256>>>(fm_w, Ah + 2359296, Al + 2359296, 65536);
    split1<<<(65536 + 255) / 256, 256>>>(fs_w, Ah + 2424832, Al + 2424832, 65536);
    split1<<<(256 * NPIX + 255) / 256, 256>>>(llf, llfh, llfl, 256 * NPIX);
    transpose_x_h<<<dim3(32, 8), dim3(32, 8)>>>(x);
    transpose_act_h<<<dim3(512, 8), dim3(32, 8)>>>(llf, fh);     // llfT fp16
    border_zero_cf<<<(516 * 256 + 255) / 256, 256>>>();
    zoff_k<<<dim3(8, 9), 128>>>(p_w, x);
    // 2. offsets xu part -> g_off (static bilinear gather of Zoff)
    gather_off<<<NPIX / 8, dim3(32, 8)>>>();
    // 3. v = sigmoid(fm_w @ llfT) -> g_v [c][pix]   (HMMA, 2-term)
    mma_gemm<10,0,2,1><<<dim3(128, 2), 256, GEMM_SMEM>>>(
        Ah + 2359296, Al + 2359296, fh, nullptr, vv, nullptr, 256, 256, 256, NPIX, 0, 0,
        nullptr, nullptr);
    // 3b. vT per channel fp16 hi/lo
    transpose_v_h2<<<dim3(4, 4, 256), dim3(32, 8)>>>();
    // 4. u[c] = llf[c] @ v[c] + llf[c]   (HMMA, 3-term exact)
    mma_gemm<13,0,2,2><<<dim3(1, 1, 256), 256, GEMM_SMEM>>>(
        llfh, llfl, vth, vtl, uu, nullptr, 128, 128, 128, NPIX, NPIX, NPIX,
        llf, nullptr);
    // 4b. uT fp16 hi + lo (exact)
    transpose_act_h2<<<dim3(512, 8), dim3(32, 8)>>>(uu, u1h, ul);
    // 5. Cf = fs_w @ uT -> cc[256:512] + CfT fp32 -> g_v + padded fp16 cfh (fused)
    mma_gemm<12,0,2,2><<<dim3(128, 2), 256, GEMM_SMEM>>>(
        Ah + 2424832, Al + 2424832, u1h, ul, cc + (size_t)256 * NPIX, vv, 256, 256, 256,
        NPIX, 0, 0, nullptr, nullptr);
    // 6. offsets Cf part accumulates onto g_off, + bias  (fp32, K=2304)
    gemm_off<<<NPIX / 128, 512>>>(p_w, p_b);
    // 7. bilinear coords/weights
    coords_k<<<9 * NPIX / 256, 256>>>();
    // 8. Z[kp] = (dc_w_xu_kp @ x32^T)^T  (tiny GEMM, 1024 cols, 1-term)
    mma_gemm<5,0,1,1><<<dim3(8, 2, 9), 256, GEMM_SMEM>>>(
        Ah, Al, xh, nullptr, nullptr, Z, 256, 4608, 256, 1024, 512, 0, nullptr, nullptr);
    // 9. Y[kp] = (dc_w_cf_kp @ Cfp^T)^T + upsample(Z[kp]) -> fp16 (1-term)
    mma_gemm<7,0,1,1><<<dim3(QPAD / 128, 2, 9), 256, GEMM_SMEM>>>(
        Ah + 256, Al + 256, cfh, nullptr, nullptr, Y, 256, 4608, 256, QPAD, 512, 0,
        Z, nullptr);
    // 10. famT = gathersum(Y) + CfT -> fp16 plane (overwrites llfT region)
    gathersum<<<NPIX, 256>>>(Y, vv);
    // 11. up1 = relu(bn1(lc1 (*) fam)) -> out + up1T fp16 plane (implicit im2col, 1-term)
    mma_gemm<8,1,1,1><<<dim3(128, 2), 256, GEMM_SMEM>>>(
        Ah + 1179648, Al + 1179648, fh, nullptr, out, u1h, 2304, 2304, 0, NPIX, 0, 0,
        bns, bnb);
    // 12. up2 = relu(bn2(lc2 (*) up1)) -> out[256*NPIX:] (implicit im2col, 1-term)
    mma_gemm<3,1,1,1><<<dim3(128, 2), 256, GEMM_SMEM>>>(
        Ah + 1769472, Al + 1769472, u1h, nullptr, out + (size_t)256 * NPIX, nullptr,
        2304, 2304, 0, NPIX, 0, 0, bns + 256, bnb + 256);
}

// round 17
// speedup vs baseline: 1.2562x; 1.0584x over previous
#include <cuda_runtime.h>
#include <cuda_bf16.h>
#include <cuda_fp16.h>
#include <math.h>
#include <stdint.h>

#define NPIX 16384          // 128*128
#define QPAD 17024          // 16900 padded positions rounded up to 128 multiple

// ---------------- static device scratch (no allocations allowed) ----------------
__device__ __align__(16) float  g_cc  [512 * NPIX];          // only [256:512] = Cf used now
__device__ __align__(16) float  g_v   [256 * NPIX];          // v; then CfT
__device__ __align__(16) float  g_u   [256 * NPIX];          // u; then Z[9][1024][256]
__device__ __align__(16) float  g_off [ 18 * NPIX];
__device__ __align__(16) int4   g_idx [9 * NPIX];
__device__ __align__(16) float4 g_wt  [9 * NPIX];
__device__ __align__(16) float  g_bnscale[512];
__device__ __align__(16) float  g_bnbias [512];
__device__ __align__(16) float  g_zoff[9 * 1024 * 32];       // Zoff[kp][s][o<18]
// fp16 single-plane operands
__device__ __align__(16) __half g_cfh[QPAD * 256];           // padded Cf map [q][256]
__device__ __align__(16) __half g_xh [1024 * 256];           // x32 transposed [s][256]
__device__ __align__(16) __half g_ul [NPIX * 256];           // uT lo plane
__device__ __align__(16) __half g_llfh[256 * NPIX];          // llf hi (chan mma A)
__device__ __align__(16) __half g_llfl[256 * NPIX];          // llf lo
__device__ __align__(16) __half g_vth[256 * NPIX];           // v per-channel transposed hi
__device__ __align__(16) __half g_vtl[256 * NPIX];           // v per-channel transposed lo
// workspace: Y[9][QPAD][256] fp16, then famT / up1T fp16 planes
#define Y_BYTES   ((size_t)9 * QPAD * 256 * 2)
#define PLANE_SZ  ((size_t)NPIX * 256 * 2)
#define FH_OFF    (Y_BYTES)
#define U1H_OFF   (Y_BYTES + PLANE_SZ)
__device__ __align__(16) char g_ws[Y_BYTES + 2 * PLANE_SZ];
// fp16 hi/lo weight planes: dc @0, lc1 @1179648, lc2 @1769472, fm @2359296, fs @2424832
__device__ __align__(16) __half g_Ah[2490368];
__device__ __align__(16) __half g_Al[2490368];

// ---------------- PTX helpers (baseline compute_103 ISA only) ----------------
__device__ __forceinline__ uint32_t smem_u32(const void* p) {
    uint32_t a;
    asm("{ .reg .u64 t; cvta.to.shared.u64 t, %1; cvt.u32.u64 %0, t; }" : "=r"(a) : "l"(p));
    return a;
}
#define CP_ASYNC16(dst, src) \
    asm volatile("cp.async.cg.shared.global [%0], [%1], 16;" :: "r"(dst), "l"(src))
#define CP_ASYNC16Z(dst, src, sz) \
    asm volatile("cp.async.cg.shared.global [%0], [%1], 16, %2;" :: "r"(dst), "l"(src), "r"(sz))
#define CP_COMMIT() asm volatile("cp.async.commit_group;")
#define CP_WAIT2()  asm volatile("cp.async.wait_group 2;" ::: "memory")
#define CP_WAIT1()  asm volatile("cp.async.wait_group 1;" ::: "memory")
#define CP_WAIT0()  asm volatile("cp.async.wait_group 0;" ::: "memory")

__device__ __forceinline__ void ldsm4(uint32_t r[4], uint32_t addr) {
    asm volatile("ldmatrix.sync.aligned.m8n8.x4.shared.b16 {%0,%1,%2,%3}, [%4];"
                 : "=r"(r[0]), "=r"(r[1]), "=r"(r[2]), "=r"(r[3]) : "r"(addr));
}
__device__ __forceinline__ void mma_f16(float c[4], const uint32_t a[4],
                                        uint32_t b0, uint32_t b1) {
    asm volatile("mma.sync.aligned.m16n8k16.row.col.f32.f16.f16.f32 "
                 "{%0,%1,%2,%3}, {%4,%5,%6,%7}, {%8,%9}, {%0,%1,%2,%3};"
                 : "+f"(c[0]), "+f"(c[1]), "+f"(c[2]), "+f"(c[3])
                 : "r"(a[0]), "r"(a[1]), "r"(a[2]), "r"(a[3]), "r"(b0), "r"(b1));
}

// ---------------- BN coefficient precompute ----------------
__global__ void bncoef_k(const float* __restrict__ g1, const float* __restrict__ b1,
                         const float* __restrict__ m1, const float* __restrict__ v1,
                         const float* __restrict__ g2, const float* __restrict__ b2,
                         const float* __restrict__ m2, const float* __restrict__ v2)
{
    int i = threadIdx.x;
    if (i < 256) {
        float s = g1[i] / sqrtf(v1[i] + 1e-5f);
        g_bnscale[i] = s;
        g_bnbias[i]  = b1[i] - m1[i] * s;
    } else {
        int j = i - 256;
        float s = g2[j] / sqrtf(v2[j] + 1e-5f);
        g_bnscale[i] = s;
        g_bnbias[i]  = b2[j] - m2[j] * s;
    }
}

// ---------------- weight fp16 hi/lo split with K permutation: k = kp*C + c ----------------
__global__ void split_perm(const float* __restrict__ w, __half* __restrict__ hi,
                           __half* __restrict__ lo, int C, int n)
{
    int t = blockIdx.x * 256 + threadIdx.x;
    if (t >= n) return;
    int K = C * 9;
    int o = t / K, r = t - o * K;
    int c = r / 9, kp = r - c * 9;
    int dst = o * K + kp * C + c;
    float v = w[t];
    __half h = __float2half(v);
    hi[dst] = h;
    lo[dst] = __float2half(v - __half2float(h));
}

// ---------------- plain fp16 hi/lo split ----------------
__global__ void split1(const float* __restrict__ w, __half* __restrict__ hi,
                       __half* __restrict__ lo, int n)
{
    int t = blockIdx.x * 256 + threadIdx.x;
    if (t >= n) return;
    float v = w[t];
    __half h = __float2half(v);
    hi[t] = h;
    lo[t] = __float2half(v - __half2float(h));
}

// ---------------- transpose x: x[c][s] -> xh[s][256] fp16 ----------------
__global__ void transpose_x_h(const float* __restrict__ x)
{
    __shared__ float sm[32][33];
    int s0 = blockIdx.x * 32, c0 = blockIdx.y * 32;
    int tx = threadIdx.x, ty = threadIdx.y;     // 32 x 8
#pragma unroll
    for (int i = 0; i < 4; i++)
        sm[ty + 8 * i][tx] = x[(c0 + ty + 8 * i) * 1024 + s0 + tx];
    __syncthreads();
#pragma unroll
    for (int i = 0; i < 4; i++)
        g_xh[(s0 + ty + 8 * i) * 256 + c0 + tx] = __float2half(sm[tx][ty + 8 * i]);
}

// ---------------- llf fused prep: hi/lo planes (same layout) + transposed fp16 plane ----
__global__ void llf_prep(const float* __restrict__ llf)
{
    __shared__ float sm[32][33];
    __half* fh = (__half*)(g_ws + FH_OFF);
    int p0 = blockIdx.x * 32, c0 = blockIdx.y * 32;
    int tx = threadIdx.x, ty = threadIdx.y;     // 32 x 8
#pragma unroll
    for (int i = 0; i < 4; i++) {
        size_t o = (size_t)(c0 + ty + 8 * i) * NPIX + p0 + tx;
        float v = llf[o];
        sm[ty + 8 * i][tx] = v;
        __half h = __float2half(v);
        g_llfh[o] = h;
        g_llfl[o] = __float2half(v - __half2float(h));
    }
    __syncthreads();
#pragma unroll
    for (int i = 0; i < 4; i++)
        fh[(size_t)(p0 + ty + 8 * i) * 256 + c0 + tx] = __float2half(sm[tx][ty + 8 * i]);
}

// ---------------- transpose activation -> fp16 hi + lo planes ----------------
__global__ void transpose_act_h2(const float* __restrict__ src,
                                 __half* __restrict__ hi, __half* __restrict__ lo)
{
    __shared__ float sm[32][33];
    int p0 = blockIdx.x * 32, c0 = blockIdx.y * 32;
    int tx = threadIdx.x, ty = threadIdx.y;     // 32 x 8
#pragma unroll
    for (int i = 0; i < 4; i++)
        sm[ty + 8 * i][tx] = src[(size_t)(c0 + ty + 8 * i) * NPIX + p0 + tx];
    __syncthreads();
#pragma unroll
    for (int i = 0; i < 4; i++) {
        float v = sm[tx][ty + 8 * i];
        __half h = __float2half(v);
        size_t o = (size_t)(p0 + ty + 8 * i) * 256 + c0 + tx;
        hi[o] = h;
        lo[o] = __float2half(v - __half2float(h));
    }
}

// ---------------- per-channel transpose v -> vT fp16 hi/lo: vt[c][a][b] = v[c][b][a] ----
__global__ void transpose_v_h2()
{
    __shared__ float sm[32][33];
    int c  = blockIdx.z;
    int h0 = blockIdx.x * 32, w0 = blockIdx.y * 32;
    int tx = threadIdx.x, ty = threadIdx.y;     // 32 x 8
    const float* src = g_v + (size_t)c * NPIX;
#pragma unroll
    for (int i = 0; i < 4; i++)
        sm[ty + 8 * i][tx] = src[(h0 + ty + 8 * i) * 128 + w0 + tx];
    __syncthreads();
#pragma unroll
    for (int i = 0; i < 4; i++) {
        float v = sm[tx][ty + 8 * i];           // = v[c][h0+tx][w0+ty+8i]
        __half h = __float2half(v);
        size_t o = (size_t)c * NPIX + (w0 + ty + 8 * i) * 128 + h0 + tx;
        g_vth[o] = h;
        g_vtl[o] = __float2half(v - __half2float(h));
    }
}

// ---------------- Zoff[kp][s][o] = sum_c p_w[o][c][kp] * x[c][s]  (fp32, xu half) -------
__global__ void __launch_bounds__(128) zoff_k(const float* __restrict__ pw,
                                              const float* __restrict__ x)
{
    __shared__ float wsm[4608];      // [o][c] 18x256
    int kp = blockIdx.y;
    int s  = blockIdx.x * 128 + threadIdx.x;
    for (int i = threadIdx.x; i < 4608; i += 128) {
        int o = i >> 8, c = i & 255;
        wsm[i] = pw[o * 4608 + c * 9 + kp];
    }
    __syncthreads();
    float acc[18];
#pragma unroll
    for (int o = 0; o < 18; o++) acc[o] = 0.0f;
#pragma unroll 4
    for (int c = 0; c < 256; c++) {
        float xv = x[c * 1024 + s];
#pragma unroll
        for (int o = 0; o < 18; o++) acc[o] = fmaf(wsm[o * 256 + c], xv, acc[o]);
    }
#pragma unroll
    for (int o = 0; o < 18; o++)
        g_zoff[((size_t)kp * 1024 + s) * 32 + o] = acc[o];
}

// ---------------- offsets xu part: static bilinear gather of Zoff -> g_off ----------
__global__ void gather_off()
{
    int o  = threadIdx.x;                       // 0..31, active < 18
    int px = blockIdx.x * 8 + threadIdx.y;
    int h = px >> 7, w = px & 127;
    if (o >= 18) return;
    float acc = 0.0f;
#pragma unroll
    for (int kp = 0; kp < 9; kp++) {
        int kh = kp / 3, kw = kp - kh * 3;
        int ih = h + kh - 1, iw = w + kw - 1;
        if ((unsigned)ih < 128u && (unsigned)iw < 128u) {
            const float sc = 31.0f / 127.0f;
            float fy = ih * sc, fx = iw * sc;
            int y0 = (int)floorf(fy); int y1 = min(y0 + 1, 31);
            int x0 = (int)floorf(fx); int x1 = min(x0 + 1, 31);
            float wy = fy - (float)y0, wx = fx - (float)x0;
            const float* zb = g_zoff + (size_t)kp * 1024 * 32 + o;
            float v00 = zb[(y0 * 32 + x0) * 32], v01 = zb[(y0 * 32 + x1) * 32];
            float v10 = zb[(y1 * 32 + x0) * 32], v11 = zb[(y1 * 32 + x1) * 32];
            float r0 = v00 * (1.0f - wy) + v10 * wy;
            float r1 = v01 * (1.0f - wy) + v11 * wy;
            acc += r0 * (1.0f - wx) + r1 * wx;
        }
    }
    g_off[o * NPIX + px] = acc;
}

// ---------------- offsets Cf part (fp32, kp-outer, K=2304), accumulates onto g_off ------
__global__ void __launch_bounds__(512) gemm_off(const float* __restrict__ A,
                                                const float* __restrict__ bias)
{
    const int K = 4608;
    __shared__ float Ash[4][16][20];
    __shared__ float red[4][18][128];
    int tid  = threadIdx.x;
    int g    = tid >> 7;            // Cf channel group 0..3 (64 channels each)
    int lane = tid & 127;
    int pix  = blockIdx.x * 128 + lane;
    int h = pix >> 7, w = pix & 127;

    float acc[18];
#pragma unroll
    for (int o = 0; o < 18; o++) acc[o] = 0.0f;

    for (int kp = 0; kp < 9; kp++) {
        int kh = kp / 3, kw = kp - kh * 3;
        int ih = h + kh - 1, iw = w + kw - 1;
        bool ok = ((unsigned)ih < 128u) && ((unsigned)iw < 128u);
        const float* bptr = g_cc + ((size_t)(256 + g * 64) << 14) + (ih << 7) + iw;
        for (int c0 = 0; c0 < 64; c0 += 16) {
            for (int i = lane; i < 288; i += 128) {
                int o = i / 16, cq = i % 16;
                Ash[g][cq][o] = A[o * K + (256 + g * 64 + c0 + cq) * 9 + kp];
            }
            __syncthreads();
            if (ok) {
#pragma unroll 4
                for (int cq = 0; cq < 16; cq++) {
                    float b = bptr[(size_t)(c0 + cq) << 14];
#pragma unroll
                    for (int o4 = 0; o4 < 4; o4++) {
                        float4 w4 = *(const float4*)&Ash[g][cq][o4 * 4];
                        acc[o4 * 4 + 0] = fmaf(w4.x, b, acc[o4 * 4 + 0]);
                        acc[o4 * 4 + 1] = fmaf(w4.y, b, acc[o4 * 4 + 1]);
                        acc[o4 * 4 + 2] = fmaf(w4.z, b, acc[o4 * 4 + 2]);
                        acc[o4 * 4 + 3] = fmaf(w4.w, b, acc[o4 * 4 + 3]);
                    }
                    float2 w2 = *(const float2*)&Ash[g][cq][16];
                    acc[16] = fmaf(w2.x, b, acc[16]);
                    acc[17] = fmaf(w2.y, b, acc[17]);
                }
            }
            __syncthreads();
        }
    }
#pragma unroll
    for (int o = 0; o < 18; o++) red[g][o][lane] = acc[o];
    __syncthreads();
    if (g == 0) {
#pragma unroll
        for (int o = 0; o < 18; o++) {
            float s = g_off[o * NPIX + pix]
                    + red[0][o][lane] + red[1][o][lane] + red[2][o][lane] + red[3][o][lane]
                    + bias[o];
            g_off[o * NPIX + pix] = s;
        }
    }
}

// ---------------- zero border rows of cfh ----------------
__global__ void border_zero_cf()
{
    int t = blockIdx.x * 256 + threadIdx.x;       // 516 * 256
    if (t >= 516 * 256) return;
    int b = t >> 8, c = t & 255;
    int q;
    if (b < 130)       q = b;
    else if (b < 260)  q = 129 * 130 + (b - 130);
    else {
        int r = b - 260;
        int hh = 1 + (r >> 1);
        int ww = (r & 1) ? 129 : 0;
        q = hh * 130 + ww;
    }
    g_cfh[(size_t)q * 256 + c] = __float2half(0.0f);
}

// ---------------- deform sampling coords + bilinear weights ----------------
__global__ void coords_k()
{
    int t = blockIdx.x * 256 + threadIdx.x;        // 9*NPIX, layout [k][pix]
    int pix = t & (NPIX - 1);
    int k   = t >> 14;
    int h = pix >> 7, w = pix & 127;
    float pnx = (float)(k / 3 - 1);
    float pny = (float)(k % 3 - 1);
    float px = g_off[k * NPIX + pix]       + pnx + (float)(h + 1);
    float py = g_off[(9 + k) * NPIX + pix] + pny + (float)(w + 1);
    float fx = floorf(px), fy = floorf(py);
    float x0 = fminf(fmaxf(fx,        0.0f), 129.0f);
    float x1 = fminf(fmaxf(fx + 1.0f, 0.0f), 129.0f);
    float y0 = fminf(fmaxf(fy,        0.0f), 129.0f);
    float y1 = fminf(fmaxf(fy + 1.0f, 0.0f), 129.0f);
    float pxc = fminf(fmaxf(px, 0.0f), 129.0f);
    float pyc = fminf(fmaxf(py, 0.0f), 129.0f);
    float glt = (1.0f + (x0 - pxc)) * (1.0f + (y0 - pyc));
    float grb = (1.0f - (x1 - pxc)) * (1.0f - (y1 - pyc));
    float glb = (1.0f + (x0 - pxc)) * (1.0f - (y1 - pyc));
    float grt = (1.0f - (x1 - pxc)) * (1.0f + (y0 - pyc));
    int ix0 = (int)x0, ix1 = (int)x1, iy0 = (int)y0, iy1 = (int)y1;
    g_idx[t] = make_int4(ix0 * 130 + iy0, ix1 * 130 + iy1, ix0 * 130 + iy1, ix1 * 130 + iy0);
    g_wt[t]  = make_float4(glt, grb, glb, grt);
}

// ---------------- gather-sum (vectorized): 1 warp/pixel, 8 ch/lane ----------------
__global__ void __launch_bounds__(256) gathersum(const __half* __restrict__ Y,
                                                 const float* __restrict__ CfT)
{
    __half* fh = (__half*)(g_ws + FH_OFF);
    int pix  = blockIdx.x * 8 + (threadIdx.x >> 5);
    int lane = threadIdx.x & 31;

    float acc[8];
    const float4* cf = (const float4*)(CfT + (size_t)pix * 256 + lane * 8);
    float4 c0 = cf[0], c1 = cf[1];
    acc[0] = c0.x; acc[1] = c0.y; acc[2] = c0.z; acc[3] = c0.w;
    acc[4] = c1.x; acc[5] = c1.y; acc[6] = c1.z; acc[7] = c1.w;

#pragma unroll
    for (int kp = 0; kp < 9; kp++) {
        int4   id = g_idx[kp * NPIX + pix];
        float4 w  = g_wt [kp * NPIX + pix];
        const __half* Yk = Y + (size_t)kp * QPAD * 256 + lane * 8;
        int   idx4[4] = {id.x, id.y, id.z, id.w};
        float wt4[4]  = {w.x, w.y, w.z, w.w};
#pragma unroll
        for (int tp = 0; tp < 4; tp++) {
            uint4 rv = *(const uint4*)(Yk + (size_t)idx4[tp] * 256);
            const __half2* hp = (const __half2*)&rv;
            float wgt = wt4[tp];
#pragma unroll
            for (int j = 0; j < 4; j++) {
                float2 f = __half22float2(hp[j]);
                acc[j * 2 + 0] = fmaf(wgt, f.x, acc[j * 2 + 0]);
                acc[j * 2 + 1] = fmaf(wgt, f.y, acc[j * 2 + 1]);
            }
        }
    }
    __half2 o[4];
    o[0] = __floats2half2_rn(acc[0], acc[1]);
    o[1] = __floats2half2_rn(acc[2], acc[3]);
    o[2] = __floats2half2_rn(acc[4], acc[5]);
    o[3] = __floats2half2_rn(acc[6], acc[7]);
    *(uint4*)(fh + (size_t)pix * 256 + lane * 8) = *(uint4*)o;
}

// ---------------- HMMA fp16 GEMM ----------------
// NT=2: A = Ah + Al (weights exact);  NT=1: A = Ah only
// BT=2: B = Bh + Bl (terms Ah*Bh + Al*Bh + Ah*Bl) -> 4-plane, 2-stage
// IMC 1: B operand is implicit 3x3 im2col over plane [pix][256]
// EPI 3:  relu(x*e1[row]+e2[row]) -> C[m][NPIX]
// EPI 8:  EPI3 + transposed fp16 plane Ct
// EPI 5:  raw -> transposed fp32 Ct (nbase = zz*nq + bcol)
// EPI 7:  raw + bilinear-upsampled Z (e1 = Z base) -> transposed fp16 Ct
// EPI 10: sigmoid -> normal store C only
// EPI 12: raw -> normal C + transposed fp32 Ct + padded fp16 g_cfh
// EPI 13: per-channel (zz=c): u = acc + e1[zz*NPIX + m*128 + n] -> C[zz*NPIX + m*128+n]
#define BK        32
#define ASTRIDE   40
#define PLANE_B   (128 * ASTRIDE * 2)      // 10240 B
#define GEMM_SMEM (9 * PLANE_B)            // 92160 B

template<int IMC, int NT, int BT>
__device__ __forceinline__ void issue_stage(
    uint32_t sb, int stage, const __half* __restrict__ pA_h,
    const __half* __restrict__ pA_l, const __half* __restrict__ pB,
    const __half* __restrict__ pBl,
    int sA, int sB, int k0, int tid, int bcol)
{
    const int STG = ((BT == 2) ? 4 : 3) * PLANE_B;
    uint32_t stb = sb + stage * STG;
    int kh = 0, kw = 0, cbase = 0;
    if (IMC) {
        int kp = k0 >> 8;
        kh = kp / 3; kw = kp - kh * 3;
        cbase = k0 & 255;
    }
#pragma unroll
    for (int q = 0; q < 2; q++) {
        int id  = tid * 2 + q;
        int row = id >> 2, seg = id & 3;
        uint32_t doff = (row * ASTRIDE + seg * 8) * 2;
        size_t aoff = (size_t)row * sA + k0 + seg * 8;
        CP_ASYNC16(stb + doff, pA_h + aoff);
        if (NT == 2) CP_ASYNC16(stb + PLANE_B + doff, pA_l + aoff);
        if (IMC) {
            int pix = bcol + row;
            int hh = pix >> 7, ww = pix & 127;
            int ih = hh + kh - 1, iw = ww + kw - 1;
            bool ok = ((unsigned)ih < 128u) && ((unsigned)iw < 128u);
            size_t boff = ok ? ((size_t)(ih * 128 + iw) * 256 + cbase + seg * 8) : 0;
            unsigned sz = ok ? 16u : 0u;
            CP_ASYNC16Z(stb + 2 * PLANE_B + doff, pB + boff, sz);
        } else {
            size_t boff = (size_t)row * sB + k0 + seg * 8;
            CP_ASYNC16(stb + 2 * PLANE_B + doff, pB + boff);
            if (BT == 2) CP_ASYNC16(stb + 3 * PLANE_B + doff, pBl + boff);
        }
    }
    CP_COMMIT();
}

template<int EPI, int IMC, int NT, int BT>
__global__ void __launch_bounds__(256, 2) mma_gemm(
    const __half* __restrict__ Ah, const __half* __restrict__ Al,
    const __half* __restrict__ B, const __half* __restrict__ Bl,
    float* __restrict__ C, void* __restrict__ Ct,
    int K, int sA, int sB, int nq, int zstrA, int zstrB,
    const float* __restrict__ e1, const float* __restrict__ e2)
{
    extern __shared__ char sm[];
    uint32_t sb = smem_u32(sm);
    const int tid = threadIdx.x;
    const int wid = tid >> 5, lane = tid & 31;
    const int wr = wid >> 2, wc = wid & 3;
    const int brow = blockIdx.y * 128, bcol = blockIdx.x * 128;
    const int zz = blockIdx.z;
    const int STG  = ((BT == 2) ? 4 : 3) * PLANE_B;
    const int NSTG = (BT == 2) ? 2 : 3;

    const __half* pA_h = Ah + (size_t)brow * sA + (size_t)zz * zstrA;
    const __half* pA_l = Al + (size_t)brow * sA + (size_t)zz * zstrA;
    const __half* pB   = IMC ? B : B + (size_t)bcol * sB + (size_t)zz * zstrB;
    const __half* pBl  = (BT == 2) ? Bl + (size_t)bcol * sB + (size_t)zz * zstrB : nullptr;

    float acc[4][4][4];
#pragma unroll
    for (int i = 0; i < 4; i++)
#pragma unroll
        for (int j = 0; j < 4; j++)
#pragma unroll
            for (int q = 0; q < 4; q++) acc[i][j][q] = 0.0f;

    const int sub = lane >> 3, rr = lane & 7;
    const int am = wr * 64 + (sub & 1) * 8 + rr;
    const int ak = (sub >> 1) * 8;
    const int bn = wc * 32 + (sub >> 1) * 8 + rr;
    const int bk = (sub & 1) * 8;

    const int NC = K / BK;
    issue_stage<IMC, NT, BT>(sb, 0, pA_h, pA_l, pB, pBl, sA, sB, 0, tid, bcol);
    issue_stage<IMC, NT, BT>(sb, 1, pA_h, pA_l, pB, pBl, sA, sB, BK, tid, bcol);

    for (int ci = 0; ci < NC; ci++) {
        if (NSTG == 3) {
            if (ci + 2 < NC) {
                issue_stage<IMC, NT, BT>(sb, (ci + 2) % 3, pA_h, pA_l, pB, pBl,
                                         sA, sB, (ci + 2) * BK, tid, bcol);
                CP_WAIT2();
            } else if (ci + 1 < NC) {
                CP_WAIT1();
            } else {
                CP_WAIT0();
            }
        } else {
            if (ci + 1 < NC) CP_WAIT1(); else CP_WAIT0();
        }
        __syncthreads();

        uint32_t stb = sb + (ci % NSTG) * STG;
#pragma unroll
        for (int ks = 0; ks < 2; ks++) {
            uint32_t ah[4][4], al[4][4], bh[4][2], bl[4][2];
#pragma unroll
            for (int mt = 0; mt < 4; mt++) {
                uint32_t aoff = ((am + mt * 16) * ASTRIDE + ks * 16 + ak) * 2;
                ldsm4(ah[mt], stb + aoff);
                if (NT == 2) ldsm4(al[mt], stb + PLANE_B + aoff);
            }
#pragma unroll
            for (int ntp = 0; ntp < 2; ntp++) {
                uint32_t boff = ((bn + ntp * 16) * ASTRIDE + ks * 16 + bk) * 2;
                uint32_t rh[4];
                ldsm4(rh, stb + 2 * PLANE_B + boff);
                bh[ntp * 2 + 0][0] = rh[0]; bh[ntp * 2 + 0][1] = rh[1];
                bh[ntp * 2 + 1][0] = rh[2]; bh[ntp * 2 + 1][1] = rh[3];
                if (BT == 2) {
                    uint32_t rl[4];
                    ldsm4(rl, stb + 3 * PLANE_B + boff);
                    bl[ntp * 2 + 0][0] = rl[0]; bl[ntp * 2 + 0][1] = rl[1];
                    bl[ntp * 2 + 1][0] = rl[2]; bl[ntp * 2 + 1][1] = rl[3];
                }
            }
#pragma unroll
            for (int mt = 0; mt < 4; mt++)
#pragma unroll
                for (int nt = 0; nt < 4; nt++) {
                    mma_f16(acc[mt][nt], ah[mt], bh[nt][0], bh[nt][1]);
                    if (NT == 2) mma_f16(acc[mt][nt], al[mt], bh[nt][0], bh[nt][1]);
                    if (BT == 2) mma_f16(acc[mt][nt], ah[mt], bl[nt][0], bl[nt][1]);
                }
        }
        __syncthreads();
        if (NSTG == 2 && ci + 2 < NC)
            issue_stage<IMC, NT, BT>(sb, ci % 2, pA_h, pA_l, pB, pBl,
                                     sA, sB, (ci + 2) * BK, tid, bcol);
    }

    // ---------------- epilogue ----------------
    const int gid = lane >> 2, t4 = lane & 3;
    float* smf = (float*)sm;                        // stride 132 -> 67584 B
#pragma unroll
    for (int mt = 0; mt < 4; mt++) {
        int ml = wr * 64 + mt * 16 + gid;
        int m0 = brow + ml;
#pragma unroll
        for (int nt = 0; nt < 4; nt++) {
            int nl = wc * 32 + nt * 8 + t4 * 2;
            int n0 = bcol + nl;
            float v0, v1, v2, v3;
            if (EPI == 5 || EPI == 7 || EPI == 12) {
                v0 = acc[mt][nt][0]; v1 = acc[mt][nt][1];
                v2 = acc[mt][nt][2]; v3 = acc[mt][nt][3];
            } else if (EPI == 10) {
                v0 = 1.0f / (1.0f + expf(-acc[mt][nt][0]));
                v1 = 1.0f / (1.0f + expf(-acc[mt][nt][1]));
                v2 = 1.0f / (1.0f + expf(-acc[mt][nt][2]));
                v3 = 1.0f / (1.0f + expf(-acc[mt][nt][3]));
            } else if (EPI == 13) {
                size_t cb = (size_t)zz * NPIX;
                v0 = acc[mt][nt][0] + e1[cb + (size_t)m0 * 128 + n0];
                v1 = acc[mt][nt][1] + e1[cb + (size_t)m0 * 128 + n0 + 1];
                v2 = acc[mt][nt][2] + e1[cb + (size_t)(m0 + 8) * 128 + n0];
                v3 = acc[mt][nt][3] + e1[cb + (size_t)(m0 + 8) * 128 + n0 + 1];
            } else {
                float s0 = e1[m0], b0 = e2[m0];
                float s1 = e1[m0 + 8], b1 = e2[m0 + 8];
                v0 = fmaxf(acc[mt][nt][0] * s0 + b0, 0.0f);
                v1 = fmaxf(acc[mt][nt][1] * s0 + b0, 0.0f);
                v2 = fmaxf(acc[mt][nt][2] * s1 + b1, 0.0f);
                v3 = fmaxf(acc[mt][nt][3] * s1 + b1, 0.0f);
            }
            if (EPI == 13) {
                size_t cb = (size_t)zz * NPIX;
                *(float2*)(C + cb + (size_t)m0 * 128 + n0)       = make_float2(v0, v1);
                *(float2*)(C + cb + (size_t)(m0 + 8) * 128 + n0) = make_float2(v2, v3);
            } else if (EPI == 3 || EPI == 8 || EPI == 10 || EPI == 12) {
                *(float2*)(C + (size_t)m0 * NPIX + n0)       = make_float2(v0, v1);
                *(float2*)(C + (size_t)(m0 + 8) * NPIX + n0) = make_float2(v2, v3);
            }
            if (EPI != 3 && EPI != 10 && EPI != 13) {
                smf[(nl)     * 132 + ml]     = v0;
                smf[(nl + 1) * 132 + ml]     = v1;
                smf[(nl)     * 132 + ml + 8] = v2;
                smf[(nl + 1) * 132 + ml + 8] = v3;
            }
        }
    }
    if (EPI == 3 || EPI == 10 || EPI == 13) return;
    __syncthreads();

    int4*   sQ = (int4*)(sm + 67584);
    float2* sW = (float2*)(sm + 67584 + 2048);
    if (EPI == 7) {
        if (tid < 128) {
            int q = bcol + tid;
            int4 qq = make_int4(-1, 0, 0, 0);
            float2 ww = make_float2(0.0f, 0.0f);
            if (q < 16900) {
                int i = q / 130, j = q - i * 130;
                if (i >= 1 && i <= 128 && j >= 1 && j <= 128) {
                    int h = i - 1, w = j - 1;
                    float fy = h * (31.0f / 127.0f);
                    float fx = w * (31.0f / 127.0f);
                    int y0 = (int)floorf(fy); int y1 = min(y0 + 1, 31);
                    int x0 = (int)floorf(fx); int x1 = min(x0 + 1, 31);
                    ww = make_float2(fy - (float)y0, fx - (float)x0);
                    qq = make_int4(y0 * 32 + x0, y0 * 32 + x1, y1 * 32 + x0, y1 * 32 + x1);
                }
            }
            sQ[tid] = qq; sW[tid] = ww;
        }
        __syncthreads();
    }

    size_t nbase = (size_t)zz * nq + bcol;
#pragma unroll 4
    for (int i = 0; i < 64; i++) {
        int idx = i * 256 + tid;
        int nl = idx >> 7, ml = idx & 127;
        float v = smf[nl * 132 + ml];
        if (EPI == 7) {
            int4 qq = sQ[nl];
            if (qq.x >= 0) {
                float2 ww = sW[nl];
                const float* Zk = e1 + (size_t)zz * 262144;
                int o = brow + ml;
                float r0 = Zk[qq.x * 256 + o] * (1.0f - ww.x) + Zk[qq.z * 256 + o] * ww.x;
                float r1 = Zk[qq.y * 256 + o] * (1.0f - ww.x) + Zk[qq.w * 256 + o] * ww.x;
                v += r0 * (1.0f - ww.y) + r1 * ww.y;
            }
        }
        if (EPI == 5) {
            ((float*)Ct)[(nbase + nl) * 256 + brow + ml] = v;
        } else if (EPI == 12) {
            int pix = bcol + nl;
            ((float*)Ct)[(size_t)pix * 256 + brow + ml] = v;
            int hh = pix >> 7, ww = pix & 127;
            g_cfh[(size_t)((hh + 1) * 130 + ww + 1) * 256 + brow + ml] = __float2half(v);
        } else if (EPI == 7 || EPI == 8) {
            ((__half*)Ct)[(nbase + nl) * 256 + brow + ml] = __float2half(v);
        }
    }
}

// ---------------- host launcher ----------------
extern "C" void kernel_launch(void* const* d_in, const int* in_sizes, int n_in,
                              void* d_out, int out_size)
{
    (void)in_sizes; (void)n_in; (void)out_size;
    const float* x    = (const float*)d_in[0];
    const float* llf  = (const float*)d_in[1];
    const float* fm_w = (const float*)d_in[2];
    const float* fs_w = (const float*)d_in[3];
    const float* p_w  = (const float*)d_in[4];
    const float* p_b  = (const float*)d_in[5];
    const float* dc_w = (const float*)d_in[6];
    const float* lc1w = (const float*)d_in[7];
    const float* g1 = (const float*)d_in[8],  *b1 = (const float*)d_in[9];
    const float* m1 = (const float*)d_in[10], *v1 = (const float*)d_in[11];
    const float* lc2w = (const float*)d_in[12];
    const float* g2 = (const float*)d_in[13], *b2 = (const float*)d_in[14];
    const float* m2 = (const float*)d_in[15], *v2 = (const float*)d_in[16];
    float* out = (float*)d_out;

    float *cc, *vv, *uu, *bns, *bnb;
    __half *Ah, *Al, *cfh, *xh, *ul, *llfh, *llfl, *vth, *vtl;
    char* ws;
    cudaGetSymbolAddress((void**)&cc,  g_cc);
    cudaGetSymbolAddress((void**)&vv,  g_v);
    cudaGetSymbolAddress((void**)&uu,  g_u);
    cudaGetSymbolAddress((void**)&bns, g_bnscale);
    cudaGetSymbolAddress((void**)&bnb, g_bnbias);
    cudaGetSymbolAddress((void**)&Ah,  g_Ah);
    cudaGetSymbolAddress((void**)&Al,  g_Al);
    cudaGetSymbolAddress((void**)&cfh, g_cfh);
    cudaGetSymbolAddress((void**)&xh,  g_xh);
    cudaGetSymbolAddress((void**)&ul,  g_ul);
    cudaGetSymbolAddress((void**)&llfh, g_llfh);
    cudaGetSymbolAddress((void**)&llfl, g_llfl);
    cudaGetSymbolAddress((void**)&vth, g_vth);
    cudaGetSymbolAddress((void**)&vtl, g_vtl);
    cudaGetSymbolAddress((void**)&ws,  g_ws);
    __half* Y = (__half*)ws;
    float* Z = uu;                                   // reuse g_u after uT extracted
    __half* fh   = (__half*)(ws + FH_OFF);           // llfT, then famT
    __half* u1h  = (__half*)(ws + U1H_OFF);          // uT-hi, then up1T

    cudaFuncSetAttribute(mma_gemm<3,1,1,1>,  cudaFuncAttributeMaxDynamicSharedMemorySize, GEMM_SMEM);
    cudaFuncSetAttribute(mma_gemm<8,1,1,1>,  cudaFuncAttributeMaxDynamicSharedMemorySize, GEMM_SMEM);
    cudaFuncSetAttribute(mma_gemm<5,0,1,1>,  cudaFuncAttributeMaxDynamicSharedMemorySize, GEMM_SMEM);
    cudaFuncSetAttribute(mma_gemm<7,0,1,1>,  cudaFuncAttributeMaxDynamicSharedMemorySize, GEMM_SMEM);
    cudaFuncSetAttribute(mma_gemm<12,0,2,2>, cudaFuncAttributeMaxDynamicSharedMemorySize, GEMM_SMEM);
    cudaFuncSetAttribute(mma_gemm<10,0,2,1>, cudaFuncAttributeMaxDynamicSharedMemorySize, GEMM_SMEM);
    cudaFuncSetAttribute(mma_gemm<13,0,2,2>, cudaFuncAttributeMaxDynamicSharedMemorySize, GEMM_SMEM);

    // 1. prep: BN coeffs, weight splits, transposes, Zoff
    bncoef_k<<<1, 512>>>(g1, b1, m1, v1, g2, b2, m2, v2);
    split_perm<<<(1179648 + 255) / 256, 256>>>(dc_w, Ah, Al, 512, 1179648);
    split_perm<<<(589824 + 255) / 256, 256>>>(lc1w, Ah + 1179648, Al + 1179648, 256, 589824);
    split_perm<<<(589824 + 255) / 256, 256>>>(lc2w, Ah + 1769472, Al + 1769472, 256, 589824);
    split1<<<(65536 + 255) / 256, 256>>>(fm_w, Ah + 2359296, Al + 2359296, 65536);
    split1<<<(65536 + 255) / 256, 256>>>(fs_w, Ah + 2424832, Al + 2424832, 65536);
    llf_prep<<<dim3(512, 8), dim3(32, 8)>>>(llf);    // llfh/llfl + llfT in one pass
    transpose_x_h<<<dim3(32, 8), dim3(32, 8)>>>(x);
    border_zero_cf<<<(516 * 256 + 255) / 256, 256>>>();
    zoff_k<<<dim3(8, 9), 128>>>(p_w, x);
    // 2. offsets xu part -> g_off (static bilinear gather of Zoff)
    gather_off<<<NPIX / 8, dim3(32, 8)>>>();
    // 3. v = sigmoid(fm_w @ llfT) -> g_v [c][pix]   (HMMA, 2-term)
    mma_gemm<10,0,2,1><<<dim3(128, 2), 256, GEMM_SMEM>>>(
        Ah + 2359296, Al + 2359296, fh, nullptr, vv, nullptr, 256, 256, 256, NPIX, 0, 0,
        nullptr, nullptr);
    // 3b. vT per channel fp16 hi/lo
    transpose_v_h2<<<dim3(4, 4, 256), dim3(32, 8)>>>();
    // 4. u[c] = llf[c] @ v[c] + llf[c]   (HMMA, 3-term exact)
    mma_gemm<13,0,2,2><<<dim3(1, 1, 256), 256, GEMM_SMEM>>>(
        llfh, llfl, vth, vtl, uu, nullptr, 128, 128, 128, NPIX, NPIX, NPIX,
        llf, nullptr);
    // 4b. uT fp16 hi + lo (exact)
    transpose_act_h2<<<dim3(512, 8), dim3(32, 8)>>>(uu, u1h, ul);
    // 5. Cf = fs_w @ uT -> cc[256:512] + CfT fp32 -> g_v + padded fp16 cfh (fused)
    mma_gemm<12,0,2,2><<<dim3(128, 2), 256, GEMM_SMEM>>>(
        Ah + 2424832, Al + 2424832, u1h, ul, cc + (size_t)256 * NPIX, vv, 256, 256, 256,
        NPIX, 0, 0, nullptr, nullptr);
    // 6. offsets Cf part accumulates onto g_off, + bias  (fp32, K=2304)
    gemm_off<<<NPIX / 128, 512>>>(p_w, p_b);
    // 7. bilinear coords/weights
    coords_k<<<9 * NPIX / 256, 256>>>();
    // 8. Z[kp] = (dc_w_xu_kp @ x32^T)^T  (tiny GEMM, 1024 cols, 1-term)
    mma_gemm<5,0,1,1><<<dim3(8, 2, 9), 256, GEMM_SMEM>>>(
        Ah, Al, xh, nullptr, nullptr, Z, 256, 4608, 256, 1024, 512, 0, nullptr, nullptr);
    // 9. Y[kp] = (dc_w_cf_kp @ Cfp^T)^T + upsample(Z[kp]) -> fp16 (1-term)
    mma_gemm<7,0,1,1><<<dim3(QPAD / 128, 2, 9), 256, GEMM_SMEM>>>(
        Ah + 256, Al + 256, cfh, nullptr, nullptr, Y, 256, 4608, 256, QPAD, 512, 0,
        Z, nullptr);
    // 10. famT = gathersum(Y) + CfT -> fp16 plane (overwrites llfT region)
    gathersum<<<NPIX / 8, 256>>>(Y, vv);
    // 11. up1 = relu(bn1(lc1 (*) fam)) -> out + up1T fp16 plane (implicit im2col, 1-term)
    mma_gemm<8,1,1,1><<<dim3(128, 2), 256, GEMM_SMEM>>>(
        Ah + 1179648, Al + 1179648, fh, nullptr, out, u1h, 2304, 2304, 0, NPIX, 0, 0,
        bns, bnb);
    // 12. up2 = relu(bn2(lc2 (*) up1)) -> out[256*NPIX:] (implicit im2col, 1-term)
    mma_gemm<3,1,1,1><<<dim3(128, 2), 256, GEMM_SMEM>>>(
        Ah + 1769472, Al + 1769472, u1h, nullptr, out + (size_t)256 * NPIX, nullptr,
        2304, 2304, 0, NPIX, 0, 0, bns + 256, bnb + 256);
}